// round 5
// baseline (speedup 1.0000x reference)
#include <cuda_runtime.h>
#include <math.h>

#define HH 320
#define WW 320
#define HWSZ (320*320)

// ---------------- scratch (static device globals; no allocation) -------------
__device__ float g_up[3*HWSZ];      // bicubic-upsampled query
__device__ float g_feat[64*HWSZ];   // [rf(0..31) | qf(32..63)]
__device__ float g_buf1[64*HWSZ];   // 2 images x 32 ch
__device__ float g_buf2[64*HWSZ];
__device__ float g_hid[32*HWSZ];

typedef unsigned long long u64;

// ---------------- packed f32x2 helpers (sm_103a FFMA2) -----------------------
__device__ __forceinline__ u64 pack2(float a, float b) {
    u64 r; asm("mov.b64 %0,{%1,%2};" : "=l"(r) : "f"(a), "f"(b)); return r;
}
__device__ __forceinline__ void unpack2(u64 v, float& a, float& b) {
    asm("mov.b64 {%0,%1},%2;" : "=f"(a), "=f"(b) : "l"(v));
}
__device__ __forceinline__ u64 fma2(u64 a, u64 b, u64 c) {
    u64 d; asm("fma.rn.f32x2 %0,%1,%2,%3;" : "=l"(d) : "l"(a), "l"(b), "l"(c)); return d;
}

// ---------------- bicubic x2 (A = -0.75) -------------------------------------
__device__ __forceinline__ float cubicw(float t) {
    t = fabsf(t);
    if (t <= 1.0f) return ((1.25f*t - 2.25f)*t)*t + 1.0f;
    if (t <  2.0f) return -0.75f*((((t - 5.0f)*t + 8.0f)*t) - 4.0f);
    return 0.0f;
}

__global__ void bicubic_k(const float* __restrict__ q, float* __restrict__ o) {
    int idx = blockIdx.x*256 + threadIdx.x;            // 3*320*320 exact
    int ox = idx % 320;
    int t  = idx / 320;
    int oy = t % 320;
    int c  = t / 320;
    float sy = (oy + 0.5f)*0.5f - 0.5f;
    float sx = (ox + 0.5f)*0.5f - 0.5f;
    int iy0 = (int)floorf(sy), ix0 = (int)floorf(sx);
    float wy[4], wx[4]; int jy[4], jx[4];
    #pragma unroll
    for (int k = 0; k < 4; k++) {
        int ty = iy0 - 1 + k;
        wy[k] = cubicw(sy - (float)ty);
        jy[k] = min(max(ty, 0), 159);
        int tx = ix0 - 1 + k;
        wx[k] = cubicw(sx - (float)tx);
        jx[k] = min(max(tx, 0), 159);
    }
    const float* qc = q + c*160*160;
    float s = 0.0f;
    #pragma unroll
    for (int yy = 0; yy < 4; yy++) {
        float acc = 0.0f;
        #pragma unroll
        for (int xx = 0; xx < 4; xx++)
            acc += wx[xx]*__ldg(qc + jy[yy]*160 + jx[xx]);
        s += wy[yy]*acc;
    }
    o[idx] = s;
}

// ---------------- 3x3 conv, 32->32, pad 1, dual image (gridDim.z) ------------
// tile 64x8; 256 threads; thread = 4 px x 16 co (2 co-groups).
// Input staged DUPLICATED: smem holds (v,v) u64 pairs -> LDS.64 feeds FFMA2
// directly (no pack MOVs). Weights read as LDS.128 broadcast.
// MODE 0: relu(conv)   MODE 1: lrelu(conv + skip)
#define C3_CHUNK 16
#define C3_RSD  136                       // dup row stride (floats) = 68 u64
#define C3_CISD (10*C3_RSD)               // 1360 floats per ci
#define C3_SIN  (C3_CHUNK*C3_CISD)        // 21760 floats
#define C3_SW   (C3_CHUNK*9*32)           // 4608 floats
#define C3_SMEM ((C3_SIN + C3_SW)*4)      // 105472 B

template<int MODE>
__global__ void __launch_bounds__(256, 2) conv3_k(
    const float* __restrict__ in0, const float* __restrict__ in1,
    const float* __restrict__ wt,  const float* __restrict__ bs,
    const float* __restrict__ sk0, const float* __restrict__ sk1,
    float* __restrict__ out0, float* __restrict__ out1)
{
    extern __shared__ float sm[];
    float* s_in = sm;             // [ci][10][68 u64 dup]
    float* s_w  = sm + C3_SIN;    // [ci][9][32co]
    const float* in = blockIdx.z ? in1 : in0;
    const float* sk = blockIdx.z ? sk1 : sk0;
    float* out      = blockIdx.z ? out1 : out0;
    const int tid = threadIdx.x;
    const int txg = tid & 15;          // 16 x-groups (4 px each)
    const int ty  = (tid >> 4) & 7;    // 8 rows
    const int cog = tid >> 7;          // 2 channel groups (16 co each)
    const int ox0 = blockIdx.x*64, oy0 = blockIdx.y*8;

    u64 acc[4][8];
    #pragma unroll
    for (int cp = 0; cp < 8; cp++) {
        u64 b = pack2(__ldg(bs + cog*16 + 2*cp), __ldg(bs + cog*16 + 2*cp + 1));
        #pragma unroll
        for (int p = 0; p < 4; p++) acc[p][cp] = b;
    }

    for (int c0 = 0; c0 < 32; c0 += C3_CHUNK) {
        if (c0) __syncthreads();
        // stage 66 used columns/row, duplicated as u64 (cols 66,67 unused)
        for (int i = tid; i < C3_CHUNK*10*66; i += 256) {
            int ci = i / 660, rem = i % 660;
            int r = rem / 66, cc = rem % 66;
            int y = oy0 - 1 + r, x = ox0 - 1 + cc;
            float v = (y >= 0 && y < HH && x >= 0 && x < WW) ? in[(c0+ci)*HWSZ + y*WW + x] : 0.0f;
            *(u64*)(s_in + ci*C3_CISD + r*C3_RSD + cc*2) = pack2(v, v);
        }
        for (int i = tid; i < C3_SW; i += 256) {
            int ci = i / 288, rem = i % 288;
            int k = rem >> 5, co = rem & 31;
            s_w[i] = wt[(co*32 + c0 + ci)*9 + k];
        }
        __syncthreads();

        #pragma unroll 2
        for (int ci = 0; ci < C3_CHUNK; ci++) {
            const u64* inci = (const u64*)(s_in + ci*C3_CISD) + ty*68 + txg*4;
            const u64* wci  = (const u64*)(s_w + ci*288) + cog*8;
            #pragma unroll
            for (int ky = 0; ky < 3; ky++) {
                const u64* rp = inci + ky*68;
                u64 vp[6];
                #pragma unroll
                for (int j = 0; j < 6; j++) vp[j] = rp[j];
                #pragma unroll
                for (int kx = 0; kx < 3; kx++) {
                    const ulonglong2* wq = (const ulonglong2*)(wci + (ky*3 + kx)*16);
                    u64 w[8];
                    #pragma unroll
                    for (int q = 0; q < 4; q++) {
                        ulonglong2 ww = wq[q];
                        w[2*q] = ww.x; w[2*q+1] = ww.y;
                    }
                    #pragma unroll
                    for (int p = 0; p < 4; p++)
                        #pragma unroll
                        for (int cp = 0; cp < 8; cp++)
                            acc[p][cp] = fma2(vp[p+kx], w[cp], acc[p][cp]);
                }
            }
        }
    }

    int o = (oy0 + ty)*WW + ox0 + txg*4;
    #pragma unroll
    for (int cp = 0; cp < 8; cp++) {
        int coe = cog*16 + 2*cp;
        float4 ve, vo;
        unpack2(acc[0][cp], ve.x, vo.x);
        unpack2(acc[1][cp], ve.y, vo.y);
        unpack2(acc[2][cp], ve.z, vo.z);
        unpack2(acc[3][cp], ve.w, vo.w);
        if (MODE == 0) {
            ve.x=fmaxf(ve.x,0.f); ve.y=fmaxf(ve.y,0.f); ve.z=fmaxf(ve.z,0.f); ve.w=fmaxf(ve.w,0.f);
            vo.x=fmaxf(vo.x,0.f); vo.y=fmaxf(vo.y,0.f); vo.z=fmaxf(vo.z,0.f); vo.w=fmaxf(vo.w,0.f);
        } else {
            float4 se = *(const float4*)(sk + coe*HWSZ + o);
            float4 so = *(const float4*)(sk + (coe+1)*HWSZ + o);
            ve.x+=se.x; ve.y+=se.y; ve.z+=se.z; ve.w+=se.w;
            vo.x+=so.x; vo.y+=so.y; vo.z+=so.z; vo.w+=so.w;
            ve.x=(ve.x>=0.f)?ve.x:0.2f*ve.x; ve.y=(ve.y>=0.f)?ve.y:0.2f*ve.y;
            ve.z=(ve.z>=0.f)?ve.z:0.2f*ve.z; ve.w=(ve.w>=0.f)?ve.w:0.2f*ve.w;
            vo.x=(vo.x>=0.f)?vo.x:0.2f*vo.x; vo.y=(vo.y>=0.f)?vo.y:0.2f*vo.y;
            vo.z=(vo.z>=0.f)?vo.z:0.2f*vo.z; vo.w=(vo.w>=0.f)?vo.w:0.2f*vo.w;
        }
        *(float4*)(out + coe*HWSZ + o)     = ve;
        *(float4*)(out + (coe+1)*HWSZ + o) = vo;
    }
}

// ---------------- 5x5 conv, CIN->32, pad 2, lrelu, dual image ----------------
// tile 64x8; thread = 4 px x 16 co; duplicated input staging; LDS.128 weights
#define C5_RSD 136
#define C5_CISD (12*C5_RSD)   // 1632 floats per ci

template<int CIN, int CHUNK>
__global__ void __launch_bounds__(256, 2) conv5_k(
    const float* __restrict__ in0, const float* __restrict__ in1,
    const float* __restrict__ wt,  const float* __restrict__ bs,
    float* __restrict__ out0, float* __restrict__ out1)
{
    extern __shared__ float sm[];
    float* s_in = sm;                    // [CHUNK][12][68 u64 dup]
    float* s_w  = sm + CHUNK*C5_CISD;    // [CHUNK][25][32co]
    const float* in = blockIdx.z ? in1 : in0;
    float* out      = blockIdx.z ? out1 : out0;
    const int tid = threadIdx.x;
    const int txg = tid & 15;
    const int ty  = (tid >> 4) & 7;
    const int cog = tid >> 7;
    const int ox0 = blockIdx.x*64, oy0 = blockIdx.y*8;

    u64 acc[4][8];
    #pragma unroll
    for (int cp = 0; cp < 8; cp++) {
        u64 b = pack2(__ldg(bs + cog*16 + 2*cp), __ldg(bs + cog*16 + 2*cp + 1));
        #pragma unroll
        for (int p = 0; p < 4; p++) acc[p][cp] = b;
    }

    for (int c0 = 0; c0 < CIN; c0 += CHUNK) {
        if (c0) __syncthreads();
        for (int i = tid; i < CHUNK*12*68; i += 256) {
            int ci = i / 816, rem = i % 816;
            int r = rem / 68, cc = rem % 68;
            int y = oy0 - 2 + r, x = ox0 - 2 + cc;
            float v = (y >= 0 && y < HH && x >= 0 && x < WW) ? in[(c0+ci)*HWSZ + y*WW + x] : 0.0f;
            *(u64*)(s_in + ci*C5_CISD + r*C5_RSD + cc*2) = pack2(v, v);
        }
        for (int i = tid; i < CHUNK*800; i += 256) {
            int ci = i / 800, rem = i % 800;
            int k = rem >> 5, co = rem & 31;
            s_w[i] = wt[(co*CIN + c0 + ci)*25 + k];
        }
        __syncthreads();

        for (int ci = 0; ci < CHUNK; ci++) {
            const u64* inci = (const u64*)(s_in + ci*C5_CISD) + ty*68 + txg*4;
            const u64* wci  = (const u64*)(s_w + ci*800) + cog*8;
            #pragma unroll
            for (int ky = 0; ky < 5; ky++) {
                const u64* rp = inci + ky*68;
                u64 vp[8];
                #pragma unroll
                for (int j = 0; j < 8; j++) vp[j] = rp[j];
                #pragma unroll
                for (int kx = 0; kx < 5; kx++) {
                    const ulonglong2* wq = (const ulonglong2*)(wci + (ky*5 + kx)*16);
                    u64 w[8];
                    #pragma unroll
                    for (int q = 0; q < 4; q++) {
                        ulonglong2 ww = wq[q];
                        w[2*q] = ww.x; w[2*q+1] = ww.y;
                    }
                    #pragma unroll
                    for (int p = 0; p < 4; p++)
                        #pragma unroll
                        for (int cp = 0; cp < 8; cp++)
                            acc[p][cp] = fma2(vp[p+kx], w[cp], acc[p][cp]);
                }
            }
        }
    }

    int o = (oy0 + ty)*WW + ox0 + txg*4;
    #pragma unroll
    for (int cp = 0; cp < 8; cp++) {
        int coe = cog*16 + 2*cp;
        float4 ve, vo;
        unpack2(acc[0][cp], ve.x, vo.x);
        unpack2(acc[1][cp], ve.y, vo.y);
        unpack2(acc[2][cp], ve.z, vo.z);
        unpack2(acc[3][cp], ve.w, vo.w);
        ve.x=(ve.x>=0.f)?ve.x:0.2f*ve.x; ve.y=(ve.y>=0.f)?ve.y:0.2f*ve.y;
        ve.z=(ve.z>=0.f)?ve.z:0.2f*ve.z; ve.w=(ve.w>=0.f)?ve.w:0.2f*ve.w;
        vo.x=(vo.x>=0.f)?vo.x:0.2f*vo.x; vo.y=(vo.y>=0.f)?vo.y:0.2f*vo.y;
        vo.z=(vo.z>=0.f)?vo.z:0.2f*vo.z; vo.w=(vo.w>=0.f)?vo.w:0.2f*vo.w;
        *(float4*)(out + coe*HWSZ + o)     = ve;
        *(float4*)(out + (coe+1)*HWSZ + o) = vo;
    }
}

// ---------------- fused 1x1 affine head + deformable 2x2 bilinear sampler ----
__device__ __forceinline__ int reflect_idx(int i) {  // xp coord -> x coord
    int r = i - 1;
    r = (r < 0) ? -r : r;
    r = (r > 319) ? (638 - r) : r;
    return r;
}

__global__ void sampler_k(const float* __restrict__ hid, const float* __restrict__ w2,
                          const float* __restrict__ b2, const float* __restrict__ x,
                          float* __restrict__ out) {
    __shared__ float s_w2[96];
    int tid = threadIdx.x;
    if (tid < 96) s_w2[tid] = w2[tid];
    __syncthreads();
    int p = blockIdx.x*256 + tid;                    // 102400 exact
    int h = p / WW, w = p % WW;

    float a0 = __ldg(b2 + 0), a1 = __ldg(b2 + 1), a2 = __ldg(b2 + 2);
    #pragma unroll 4
    for (int c = 0; c < 32; c++) {
        float hv = hid[c*HWSZ + p];
        a0 += hv*s_w2[c];
        a1 += hv*s_w2[32 + c];
        a2 += hv*s_w2[64 + c];
    }
    a0 = fminf(fmaxf(a0 + 1.0f, -3.0f), 3.0f);       // s_x
    a1 = fminf(fmaxf(a1 + 1.0f, -3.0f), 3.0f);       // s_y
    a2 = fminf(fmaxf(a2 + 1.0f, -3.0f), 3.0f);
    float th = (a2 - 1.0f)*1.0472f;
    float ct = cosf(th), st = sinf(th);

    int   idx[16];
    float wg[16];
    #pragma unroll
    for (int k = 0; k < 4; k++) {
        float pnx = (k & 2) ? 0.5f : -0.5f;
        float pny = (k & 1) ? 0.5f : -0.5f;
        float px = pnx*a0, py = pny*a1;
        float rx = px*ct - py*st;
        float ry = px*st + py*ct;
        float p_x = rx + 0.5f + (float)(h + 1);
        float p_y = ry + 0.5f + (float)(w + 1);
        float ltx = floorf(p_x), lty = floorf(p_y);
        float ltxc = fminf(fmaxf(ltx,        0.0f), 321.0f);
        float ltyc = fminf(fmaxf(lty,        0.0f), 321.0f);
        float rbxc = fminf(fmaxf(ltx + 1.0f, 0.0f), 321.0f);
        float rbyc = fminf(fmaxf(lty + 1.0f, 0.0f), 321.0f);
        float pxc  = fminf(fmaxf(p_x,        0.0f), 321.0f);
        float pyc  = fminf(fmaxf(p_y,        0.0f), 321.0f);
        float wlx = 1.0f + ltxc - pxc;
        float wrx = 1.0f - (rbxc - pxc);
        float wly = 1.0f + ltyc - pyc;
        float wry = 1.0f - (rbyc - pyc);
        int rl = reflect_idx((int)ltxc);
        int rr = reflect_idx((int)rbxc);
        int cl = reflect_idx((int)ltyc);
        int cr = reflect_idx((int)rbyc);
        idx[k*4+0] = rl*WW + cl;  wg[k*4+0] = wlx*wly;   // lt
        idx[k*4+1] = rr*WW + cr;  wg[k*4+1] = wrx*wry;   // rb
        idx[k*4+2] = rl*WW + cr;  wg[k*4+2] = wlx*wry;   // lb
        idx[k*4+3] = rr*WW + cl;  wg[k*4+3] = wrx*wly;   // rt
    }

    int ob = (2*h)*640 + 2*w;
    for (int c = 0; c < 64; c++) {
        const float* xc = x + c*HWSZ;
        float* oc = out + c*640*640;
        float v[4];
        #pragma unroll
        for (int k = 0; k < 4; k++) {
            v[k] = wg[k*4+0]*__ldg(xc + idx[k*4+0])
                 + wg[k*4+1]*__ldg(xc + idx[k*4+1])
                 + wg[k*4+2]*__ldg(xc + idx[k*4+2])
                 + wg[k*4+3]*__ldg(xc + idx[k*4+3]);
        }
        *(float2*)(oc + ob)       = make_float2(v[0], v[1]);
        *(float2*)(oc + ob + 640) = make_float2(v[2], v[3]);
    }
}

// ---------------- launch ------------------------------------------------------
extern "C" void kernel_launch(void* const* d_in, const int* in_sizes, int n_in,
                              void* d_out, int out_size) {
    const float* x    = (const float*)d_in[0];
    const float* qry  = (const float*)d_in[1];
    const float* ref  = (const float*)d_in[2];
    const float* c1w  = (const float*)d_in[3];
    const float* c1b  = (const float*)d_in[4];
    const float* r1w1 = (const float*)d_in[5];
    const float* r1b1 = (const float*)d_in[6];
    const float* r1w2 = (const float*)d_in[7];
    const float* r1b2 = (const float*)d_in[8];
    const float* p1w  = (const float*)d_in[9];
    const float* p1b  = (const float*)d_in[10];
    const float* prw1 = (const float*)d_in[11];
    const float* prb1 = (const float*)d_in[12];
    const float* prw2 = (const float*)d_in[13];
    const float* prb2 = (const float*)d_in[14];
    const float* p2w  = (const float*)d_in[15];
    const float* p2b  = (const float*)d_in[16];
    float* out = (float*)d_out;

    float *up, *feat, *buf1, *buf2, *hid;
    cudaGetSymbolAddress((void**)&up,   g_up);
    cudaGetSymbolAddress((void**)&feat, g_feat);
    cudaGetSymbolAddress((void**)&buf1, g_buf1);
    cudaGetSymbolAddress((void**)&buf2, g_buf2);
    cudaGetSymbolAddress((void**)&hid,  g_hid);

    const int SM3    = C3_SMEM;                       // 105472 B
    const int SM5_3  = (3*C5_CISD + 3*800)*4;         // 29184 B
    const int SM5_64 = (8*C5_CISD + 8*800)*4;         // 77824 B
    cudaFuncSetAttribute(conv3_k<0>, cudaFuncAttributeMaxDynamicSharedMemorySize, SM3);
    cudaFuncSetAttribute(conv3_k<1>, cudaFuncAttributeMaxDynamicSharedMemorySize, SM3);
    cudaFuncSetAttribute(conv5_k<3,3>,  cudaFuncAttributeMaxDynamicSharedMemorySize, SM5_3);
    cudaFuncSetAttribute(conv5_k<64,8>, cudaFuncAttributeMaxDynamicSharedMemorySize, SM5_64);

    dim3 cg2(5, 40, 2);   // 64x8 tiles, dual image
    dim3 cg1(5, 40, 1);

    // 1. bicubic upsample query 160->320
    bicubic_k<<<(3*HWSZ)/256, 256>>>(qry, up);

    // 2+3. both feature heads batched over gridDim.z
    conv5_k<3,3><<<cg2, 256, SM5_3>>>(ref, up, c1w, c1b, buf1, buf1 + 32*HWSZ);
    conv3_k<0><<<cg2, 256, SM3>>>(buf1, buf1 + 32*HWSZ, r1w1, r1b1,
                                  nullptr, nullptr, buf2, buf2 + 32*HWSZ);
    conv3_k<1><<<cg2, 256, SM3>>>(buf2, buf2 + 32*HWSZ, r1w2, r1b2,
                                  buf1, buf1 + 32*HWSZ, feat, feat + 32*HWSZ);

    // 4. fusion head
    conv5_k<64,8><<<cg1, 256, SM5_64>>>(feat, feat, p1w, p1b, buf1, buf1);
    conv3_k<0><<<cg1, 256, SM3>>>(buf1, buf1, prw1, prb1, nullptr, nullptr, buf2, buf2);
    conv3_k<1><<<cg1, 256, SM3>>>(buf2, buf2, prw2, prb2, buf1, buf1, hid, hid);

    // 5. fused 1x1 affine head + deformable sampler -> out (64,640,640)
    sampler_k<<<HWSZ/256, 256>>>(hid, p2w, p2b, x, out);
}

// round 6
// speedup vs baseline: 1.0995x; 1.0995x over previous
#include <cuda_runtime.h>
#include <math.h>

#define HH 320
#define WW 320
#define HWSZ (320*320)

// ---------------- scratch (static device globals; no allocation) -------------
__device__ float g_up[3*HWSZ];      // bicubic-upsampled query
__device__ float g_feat[64*HWSZ];   // [rf(0..31) | qf(32..63)]
__device__ float g_buf1[64*HWSZ];   // 2 images x 32 ch
__device__ float g_buf2[64*HWSZ];
__device__ float g_hid[32*HWSZ];

typedef unsigned long long u64;

// ---------------- packed f32x2 helpers (sm_103a FFMA2) -----------------------
__device__ __forceinline__ u64 pack2(float a, float b) {
    u64 r; asm("mov.b64 %0,{%1,%2};" : "=l"(r) : "f"(a), "f"(b)); return r;
}
__device__ __forceinline__ void unpack2(u64 v, float& a, float& b) {
    asm("mov.b64 {%0,%1},%2;" : "=f"(a), "=f"(b) : "l"(v));
}
__device__ __forceinline__ u64 fma2(u64 a, u64 b, u64 c) {
    u64 d; asm("fma.rn.f32x2 %0,%1,%2,%3;" : "=l"(d) : "l"(a), "l"(b), "l"(c)); return d;
}

// ---------------- bicubic x2 (A = -0.75) -------------------------------------
__device__ __forceinline__ float cubicw(float t) {
    t = fabsf(t);
    if (t <= 1.0f) return ((1.25f*t - 2.25f)*t)*t + 1.0f;
    if (t <  2.0f) return -0.75f*((((t - 5.0f)*t + 8.0f)*t) - 4.0f);
    return 0.0f;
}

__global__ void bicubic_k(const float* __restrict__ q, float* __restrict__ o) {
    int idx = blockIdx.x*256 + threadIdx.x;            // 3*320*320 exact
    int ox = idx % 320;
    int t  = idx / 320;
    int oy = t % 320;
    int c  = t / 320;
    float sy = (oy + 0.5f)*0.5f - 0.5f;
    float sx = (ox + 0.5f)*0.5f - 0.5f;
    int iy0 = (int)floorf(sy), ix0 = (int)floorf(sx);
    float wy[4], wx[4]; int jy[4], jx[4];
    #pragma unroll
    for (int k = 0; k < 4; k++) {
        int ty = iy0 - 1 + k;
        wy[k] = cubicw(sy - (float)ty);
        jy[k] = min(max(ty, 0), 159);
        int tx = ix0 - 1 + k;
        wx[k] = cubicw(sx - (float)tx);
        jx[k] = min(max(tx, 0), 159);
    }
    const float* qc = q + c*160*160;
    float s = 0.0f;
    #pragma unroll
    for (int yy = 0; yy < 4; yy++) {
        float acc = 0.0f;
        #pragma unroll
        for (int xx = 0; xx < 4; xx++)
            acc += wx[xx]*__ldg(qc + jy[yy]*160 + jx[xx]);
        s += wy[yy]*acc;
    }
    o[idx] = s;
}

// ---------------- 3x3 conv, 32->32, pad 1, dual image (gridDim.z) ------------
// tile 64x8; 256 threads; thread = 4 consecutive px x 16 channels (2 co-groups)
// Input: scalar smem (stride 68 for aligned float4). Weights: LDS.128 broadcast.
// MODE 0: relu(conv)   MODE 1: lrelu(conv + skip)
#define C3_CHUNK 16
#define C3_RS   68                      // padded row stride (floats)
#define C3_CIS  (10*C3_RS)              // 680 floats per ci
#define C3_SIN  (C3_CHUNK*C3_CIS)       // 10880 floats
#define C3_SW   (C3_CHUNK*9*32)         // 4608 floats
#define C3_SMEM ((C3_SIN + C3_SW)*4)    // 61952 B

template<int MODE>
__global__ void __launch_bounds__(256, 2) conv3_k(
    const float* __restrict__ in0, const float* __restrict__ in1,
    const float* __restrict__ wt,  const float* __restrict__ bs,
    const float* __restrict__ sk0, const float* __restrict__ sk1,
    float* __restrict__ out0, float* __restrict__ out1)
{
    extern __shared__ float sm[];
    float* s_in = sm;             // [ci][10][68 (66 used)]
    float* s_w  = sm + C3_SIN;    // [ci][9][32co]
    const float* in = blockIdx.z ? in1 : in0;
    const float* sk = blockIdx.z ? sk1 : sk0;
    float* out      = blockIdx.z ? out1 : out0;
    const int tid = threadIdx.x;
    const int txg = tid & 15;          // 16 x-groups (4 px each)
    const int ty  = (tid >> 4) & 7;    // 8 rows
    const int cog = tid >> 7;          // 2 channel groups (16 co each)
    const int ox0 = blockIdx.x*64, oy0 = blockIdx.y*8;

    u64 acc[4][8];
    #pragma unroll
    for (int cp = 0; cp < 8; cp++) {
        u64 b = pack2(__ldg(bs + cog*16 + 2*cp), __ldg(bs + cog*16 + 2*cp + 1));
        #pragma unroll
        for (int p = 0; p < 4; p++) acc[p][cp] = b;
    }

    for (int c0 = 0; c0 < 32; c0 += C3_CHUNK) {
        if (c0) __syncthreads();
        for (int i = tid; i < C3_CHUNK*10*66; i += 256) {
            int ci = i / 660, rem = i % 660;
            int r = rem / 66, cc = rem % 66;
            int y = oy0 - 1 + r, x = ox0 - 1 + cc;
            s_in[ci*C3_CIS + r*C3_RS + cc] =
                (y >= 0 && y < HH && x >= 0 && x < WW) ? in[(c0+ci)*HWSZ + y*WW + x] : 0.0f;
        }
        for (int i = tid; i < C3_SW; i += 256) {
            int ci = i / 288, rem = i % 288;
            int k = rem >> 5, co = rem & 31;
            s_w[i] = wt[(co*32 + c0 + ci)*9 + k];
        }
        __syncthreads();

        for (int ci = 0; ci < C3_CHUNK; ci++) {
            const float* base = s_in + ci*C3_CIS + ty*C3_RS + txg*4;
            const ulonglong2* wci = (const ulonglong2*)(s_w + ci*288 + cog*16);
            #pragma unroll
            for (int ky = 0; ky < 3; ky++) {
                const float* rp = base + ky*C3_RS;
                float4 v4 = *(const float4*)rp;
                float2 v2 = *(const float2*)(rp + 4);
                u64 vp[6];
                vp[0]=pack2(v4.x,v4.x); vp[1]=pack2(v4.y,v4.y); vp[2]=pack2(v4.z,v4.z);
                vp[3]=pack2(v4.w,v4.w); vp[4]=pack2(v2.x,v2.x); vp[5]=pack2(v2.y,v2.y);
                #pragma unroll
                for (int kx = 0; kx < 3; kx++) {
                    const ulonglong2* wq = wci + (ky*3 + kx)*8;   // 8 ull2 per 32-co row; cog offset folded
                    u64 w[8];
                    #pragma unroll
                    for (int q = 0; q < 4; q++) {
                        ulonglong2 ww = wq[q];
                        w[2*q] = ww.x; w[2*q+1] = ww.y;
                    }
                    #pragma unroll
                    for (int p = 0; p < 4; p++)
                        #pragma unroll
                        for (int cp = 0; cp < 8; cp++)
                            acc[p][cp] = fma2(vp[p+kx], w[cp], acc[p][cp]);
                }
            }
        }
    }

    int o = (oy0 + ty)*WW + ox0 + txg*4;
    #pragma unroll
    for (int cp = 0; cp < 8; cp++) {
        int coe = cog*16 + 2*cp;
        float4 ve, vo;
        unpack2(acc[0][cp], ve.x, vo.x);
        unpack2(acc[1][cp], ve.y, vo.y);
        unpack2(acc[2][cp], ve.z, vo.z);
        unpack2(acc[3][cp], ve.w, vo.w);
        if (MODE == 0) {
            ve.x=fmaxf(ve.x,0.f); ve.y=fmaxf(ve.y,0.f); ve.z=fmaxf(ve.z,0.f); ve.w=fmaxf(ve.w,0.f);
            vo.x=fmaxf(vo.x,0.f); vo.y=fmaxf(vo.y,0.f); vo.z=fmaxf(vo.z,0.f); vo.w=fmaxf(vo.w,0.f);
        } else {
            float4 se = *(const float4*)(sk + coe*HWSZ + o);
            float4 so = *(const float4*)(sk + (coe+1)*HWSZ + o);
            ve.x+=se.x; ve.y+=se.y; ve.z+=se.z; ve.w+=se.w;
            vo.x+=so.x; vo.y+=so.y; vo.z+=so.z; vo.w+=so.w;
            ve.x=(ve.x>=0.f)?ve.x:0.2f*ve.x; ve.y=(ve.y>=0.f)?ve.y:0.2f*ve.y;
            ve.z=(ve.z>=0.f)?ve.z:0.2f*ve.z; ve.w=(ve.w>=0.f)?ve.w:0.2f*ve.w;
            vo.x=(vo.x>=0.f)?vo.x:0.2f*vo.x; vo.y=(vo.y>=0.f)?vo.y:0.2f*vo.y;
            vo.z=(vo.z>=0.f)?vo.z:0.2f*vo.z; vo.w=(vo.w>=0.f)?vo.w:0.2f*vo.w;
        }
        *(float4*)(out + coe*HWSZ + o)     = ve;
        *(float4*)(out + (coe+1)*HWSZ + o) = vo;
    }
}

// ---------------- 5x5 conv, CIN->32, pad 2, lrelu, dual image ----------------
// tile 64x8; thread = 4 px x 16 co; scalar input smem; LDS.128 weights
template<int CIN, int CHUNK>
__global__ void __launch_bounds__(256, 2) conv5_k(
    const float* __restrict__ in0, const float* __restrict__ in1,
    const float* __restrict__ wt,  const float* __restrict__ bs,
    float* __restrict__ out0, float* __restrict__ out1)
{
    extern __shared__ float sm[];
    float* s_in = sm;                  // [CHUNK][12][68]
    float* s_w  = sm + CHUNK*816;      // [CHUNK][25][32co]
    const float* in = blockIdx.z ? in1 : in0;
    float* out      = blockIdx.z ? out1 : out0;
    const int tid = threadIdx.x;
    const int txg = tid & 15;
    const int ty  = (tid >> 4) & 7;
    const int cog = tid >> 7;
    const int ox0 = blockIdx.x*64, oy0 = blockIdx.y*8;

    u64 acc[4][8];
    #pragma unroll
    for (int cp = 0; cp < 8; cp++) {
        u64 b = pack2(__ldg(bs + cog*16 + 2*cp), __ldg(bs + cog*16 + 2*cp + 1));
        #pragma unroll
        for (int p = 0; p < 4; p++) acc[p][cp] = b;
    }

    for (int c0 = 0; c0 < CIN; c0 += CHUNK) {
        if (c0) __syncthreads();
        for (int i = tid; i < CHUNK*816; i += 256) {
            int ci = i / 816, rem = i % 816;
            int r = rem / 68, cc = rem % 68;
            int y = oy0 - 2 + r, x = ox0 - 2 + cc;
            s_in[i] = (y >= 0 && y < HH && x >= 0 && x < WW) ? in[(c0+ci)*HWSZ + y*WW + x] : 0.0f;
        }
        for (int i = tid; i < CHUNK*800; i += 256) {
            int ci = i / 800, rem = i % 800;
            int k = rem >> 5, co = rem & 31;
            s_w[i] = wt[(co*CIN + c0 + ci)*25 + k];
        }
        __syncthreads();

        for (int ci = 0; ci < CHUNK; ci++) {
            const float* base = s_in + ci*816 + ty*68 + txg*4;
            const ulonglong2* wci = (const ulonglong2*)(s_w + ci*800 + cog*16);
            #pragma unroll
            for (int ky = 0; ky < 5; ky++) {
                const float* rp = base + ky*68;
                float4 a4 = *(const float4*)rp;
                float4 b4 = *(const float4*)(rp + 4);
                u64 vp[8];
                vp[0]=pack2(a4.x,a4.x); vp[1]=pack2(a4.y,a4.y); vp[2]=pack2(a4.z,a4.z);
                vp[3]=pack2(a4.w,a4.w); vp[4]=pack2(b4.x,b4.x); vp[5]=pack2(b4.y,b4.y);
                vp[6]=pack2(b4.z,b4.z); vp[7]=pack2(b4.w,b4.w);
                #pragma unroll
                for (int kx = 0; kx < 5; kx++) {
                    const ulonglong2* wq = wci + (ky*5 + kx)*8;
                    u64 w[8];
                    #pragma unroll
                    for (int q = 0; q < 4; q++) {
                        ulonglong2 ww = wq[q];
                        w[2*q] = ww.x; w[2*q+1] = ww.y;
                    }
                    #pragma unroll
                    for (int p = 0; p < 4; p++)
                        #pragma unroll
                        for (int cp = 0; cp < 8; cp++)
                            acc[p][cp] = fma2(vp[p+kx], w[cp], acc[p][cp]);
                }
            }
        }
    }

    int o = (oy0 + ty)*WW + ox0 + txg*4;
    #pragma unroll
    for (int cp = 0; cp < 8; cp++) {
        int coe = cog*16 + 2*cp;
        float4 ve, vo;
        unpack2(acc[0][cp], ve.x, vo.x);
        unpack2(acc[1][cp], ve.y, vo.y);
        unpack2(acc[2][cp], ve.z, vo.z);
        unpack2(acc[3][cp], ve.w, vo.w);
        ve.x=(ve.x>=0.f)?ve.x:0.2f*ve.x; ve.y=(ve.y>=0.f)?ve.y:0.2f*ve.y;
        ve.z=(ve.z>=0.f)?ve.z:0.2f*ve.z; ve.w=(ve.w>=0.f)?ve.w:0.2f*ve.w;
        vo.x=(vo.x>=0.f)?vo.x:0.2f*vo.x; vo.y=(vo.y>=0.f)?vo.y:0.2f*vo.y;
        vo.z=(vo.z>=0.f)?vo.z:0.2f*vo.z; vo.w=(vo.w>=0.f)?vo.w:0.2f*vo.w;
        *(float4*)(out + coe*HWSZ + o)     = ve;
        *(float4*)(out + (coe+1)*HWSZ + o) = vo;
    }
}

// ---------------- fused 1x1 affine head + deformable 2x2 bilinear sampler ----
__device__ __forceinline__ int reflect_idx(int i) {  // xp coord -> x coord
    int r = i - 1;
    r = (r < 0) ? -r : r;
    r = (r > 319) ? (638 - r) : r;
    return r;
}

__global__ void sampler_k(const float* __restrict__ hid, const float* __restrict__ w2,
                          const float* __restrict__ b2, const float* __restrict__ x,
                          float* __restrict__ out) {
    __shared__ float s_w2[96];
    int tid = threadIdx.x;
    if (tid < 96) s_w2[tid] = w2[tid];
    __syncthreads();
    int p = blockIdx.x*256 + tid;                    // 102400 exact
    int h = p / WW, w = p % WW;

    float a0 = __ldg(b2 + 0), a1 = __ldg(b2 + 1), a2 = __ldg(b2 + 2);
    #pragma unroll 4
    for (int c = 0; c < 32; c++) {
        float hv = hid[c*HWSZ + p];
        a0 += hv*s_w2[c];
        a1 += hv*s_w2[32 + c];
        a2 += hv*s_w2[64 + c];
    }
    a0 = fminf(fmaxf(a0 + 1.0f, -3.0f), 3.0f);       // s_x
    a1 = fminf(fmaxf(a1 + 1.0f, -3.0f), 3.0f);       // s_y
    a2 = fminf(fmaxf(a2 + 1.0f, -3.0f), 3.0f);
    float th = (a2 - 1.0f)*1.0472f;
    float ct = cosf(th), st = sinf(th);

    int   idx[16];
    float wg[16];
    #pragma unroll
    for (int k = 0; k < 4; k++) {
        float pnx = (k & 2) ? 0.5f : -0.5f;
        float pny = (k & 1) ? 0.5f : -0.5f;
        float px = pnx*a0, py = pny*a1;
        float rx = px*ct - py*st;
        float ry = px*st + py*ct;
        float p_x = rx + 0.5f + (float)(h + 1);
        float p_y = ry + 0.5f + (float)(w + 1);
        float ltx = floorf(p_x), lty = floorf(p_y);
        float ltxc = fminf(fmaxf(ltx,        0.0f), 321.0f);
        float ltyc = fminf(fmaxf(lty,        0.0f), 321.0f);
        float rbxc = fminf(fmaxf(ltx + 1.0f, 0.0f), 321.0f);
        float rbyc = fminf(fmaxf(lty + 1.0f, 0.0f), 321.0f);
        float pxc  = fminf(fmaxf(p_x,        0.0f), 321.0f);
        float pyc  = fminf(fmaxf(p_y,        0.0f), 321.0f);
        float wlx = 1.0f + ltxc - pxc;
        float wrx = 1.0f - (rbxc - pxc);
        float wly = 1.0f + ltyc - pyc;
        float wry = 1.0f - (rbyc - pyc);
        int rl = reflect_idx((int)ltxc);
        int rr = reflect_idx((int)rbxc);
        int cl = reflect_idx((int)ltyc);
        int cr = reflect_idx((int)rbyc);
        idx[k*4+0] = rl*WW + cl;  wg[k*4+0] = wlx*wly;   // lt
        idx[k*4+1] = rr*WW + cr;  wg[k*4+1] = wrx*wry;   // rb
        idx[k*4+2] = rl*WW + cr;  wg[k*4+2] = wlx*wry;   // lb
        idx[k*4+3] = rr*WW + cl;  wg[k*4+3] = wrx*wly;   // rt
    }

    int ob = (2*h)*640 + 2*w;
    for (int c = 0; c < 64; c++) {
        const float* xc = x + c*HWSZ;
        float* oc = out + c*640*640;
        float v[4];
        #pragma unroll
        for (int k = 0; k < 4; k++) {
            v[k] = wg[k*4+0]*__ldg(xc + idx[k*4+0])
                 + wg[k*4+1]*__ldg(xc + idx[k*4+1])
                 + wg[k*4+2]*__ldg(xc + idx[k*4+2])
                 + wg[k*4+3]*__ldg(xc + idx[k*4+3]);
        }
        *(float2*)(oc + ob)       = make_float2(v[0], v[1]);
        *(float2*)(oc + ob + 640) = make_float2(v[2], v[3]);
    }
}

// ---------------- launch ------------------------------------------------------
extern "C" void kernel_launch(void* const* d_in, const int* in_sizes, int n_in,
                              void* d_out, int out_size) {
    const float* x    = (const float*)d_in[0];
    const float* qry  = (const float*)d_in[1];
    const float* ref  = (const float*)d_in[2];
    const float* c1w  = (const float*)d_in[3];
    const float* c1b  = (const float*)d_in[4];
    const float* r1w1 = (const float*)d_in[5];
    const float* r1b1 = (const float*)d_in[6];
    const float* r1w2 = (const float*)d_in[7];
    const float* r1b2 = (const float*)d_in[8];
    const float* p1w  = (const float*)d_in[9];
    const float* p1b  = (const float*)d_in[10];
    const float* prw1 = (const float*)d_in[11];
    const float* prb1 = (const float*)d_in[12];
    const float* prw2 = (const float*)d_in[13];
    const float* prb2 = (const float*)d_in[14];
    const float* p2w  = (const float*)d_in[15];
    const float* p2b  = (const float*)d_in[16];
    float* out = (float*)d_out;

    float *up, *feat, *buf1, *buf2, *hid;
    cudaGetSymbolAddress((void**)&up,   g_up);
    cudaGetSymbolAddress((void**)&feat, g_feat);
    cudaGetSymbolAddress((void**)&buf1, g_buf1);
    cudaGetSymbolAddress((void**)&buf2, g_buf2);
    cudaGetSymbolAddress((void**)&hid,  g_hid);

    const int SM3    = C3_SMEM;                 // 61952 B
    const int SM5_3  = (3*816 + 3*800)*4;       // 19392 B
    const int SM5_64 = (8*816 + 8*800)*4;       // 51712 B
    cudaFuncSetAttribute(conv3_k<0>, cudaFuncAttributeMaxDynamicSharedMemorySize, SM3);
    cudaFuncSetAttribute(conv3_k<1>, cudaFuncAttributeMaxDynamicSharedMemorySize, SM3);
    cudaFuncSetAttribute(conv5_k<3,3>,  cudaFuncAttributeMaxDynamicSharedMemorySize, SM5_3);
    cudaFuncSetAttribute(conv5_k<64,8>, cudaFuncAttributeMaxDynamicSharedMemorySize, SM5_64);

    dim3 cg2(5, 40, 2);   // 64x8 tiles, dual image
    dim3 cg1(5, 40, 1);

    // 1. bicubic upsample query 160->320
    bicubic_k<<<(3*HWSZ)/256, 256>>>(qry, up);

    // 2+3. both feature heads batched over gridDim.z
    conv5_k<3,3><<<cg2, 256, SM5_3>>>(ref, up, c1w, c1b, buf1, buf1 + 32*HWSZ);
    conv3_k<0><<<cg2, 256, SM3>>>(buf1, buf1 + 32*HWSZ, r1w1, r1b1,
                                  nullptr, nullptr, buf2, buf2 + 32*HWSZ);
    conv3_k<1><<<cg2, 256, SM3>>>(buf2, buf2 + 32*HWSZ, r1w2, r1b2,
                                  buf1, buf1 + 32*HWSZ, feat, feat + 32*HWSZ);

    // 4. fusion head
    conv5_k<64,8><<<cg1, 256, SM5_64>>>(feat, feat, p1w, p1b, buf1, buf1);
    conv3_k<0><<<cg1, 256, SM3>>>(buf1, buf1, prw1, prb1, nullptr, nullptr, buf2, buf2);
    conv3_k<1><<<cg1, 256, SM3>>>(buf2, buf2, prw2, prb2, buf1, buf1, hid, hid);

    // 5. fused 1x1 affine head + deformable sampler -> out (64,640,640)
    sampler_k<<<HWSZ/256, 256>>>(hid, p2w, p2b, x, out);
}

// round 7
// speedup vs baseline: 1.1122x; 1.0116x over previous
#include <cuda_runtime.h>
#include <math.h>

#define HH 320
#define WW 320
#define HWSZ (320*320)

// ---------------- scratch (static device globals; no allocation) -------------
__device__ float g_up[3*HWSZ];      // bicubic-upsampled query
__device__ float g_feat[64*HWSZ];   // [rf(0..31) | qf(32..63)]
__device__ float g_buf1[64*HWSZ];   // 2 images x 32 ch
__device__ float g_buf2[64*HWSZ];
__device__ float g_hid[32*HWSZ];

typedef unsigned long long u64;

// ---------------- packed f32x2 helpers (sm_103a FFMA2) -----------------------
__device__ __forceinline__ u64 pack2(float a, float b) {
    u64 r; asm("mov.b64 %0,{%1,%2};" : "=l"(r) : "f"(a), "f"(b)); return r;
}
__device__ __forceinline__ void unpack2(u64 v, float& a, float& b) {
    asm("mov.b64 {%0,%1},%2;" : "=f"(a), "=f"(b) : "l"(v));
}
__device__ __forceinline__ u64 fma2(u64 a, u64 b, u64 c) {
    u64 d; asm("fma.rn.f32x2 %0,%1,%2,%3;" : "=l"(d) : "l"(a), "l"(b), "l"(c)); return d;
}

// ---------------- bicubic x2 (A = -0.75) -------------------------------------
__device__ __forceinline__ float cubicw(float t) {
    t = fabsf(t);
    if (t <= 1.0f) return ((1.25f*t - 2.25f)*t)*t + 1.0f;
    if (t <  2.0f) return -0.75f*((((t - 5.0f)*t + 8.0f)*t) - 4.0f);
    return 0.0f;
}

__global__ void bicubic_k(const float* __restrict__ q, float* __restrict__ o) {
    int idx = blockIdx.x*256 + threadIdx.x;            // 3*320*320 exact
    int ox = idx % 320;
    int t  = idx / 320;
    int oy = t % 320;
    int c  = t / 320;
    float sy = (oy + 0.5f)*0.5f - 0.5f;
    float sx = (ox + 0.5f)*0.5f - 0.5f;
    int iy0 = (int)floorf(sy), ix0 = (int)floorf(sx);
    float wy[4], wx[4]; int jy[4], jx[4];
    #pragma unroll
    for (int k = 0; k < 4; k++) {
        int ty = iy0 - 1 + k;
        wy[k] = cubicw(sy - (float)ty);
        jy[k] = min(max(ty, 0), 159);
        int tx = ix0 - 1 + k;
        wx[k] = cubicw(sx - (float)tx);
        jx[k] = min(max(tx, 0), 159);
    }
    const float* qc = q + c*160*160;
    float s = 0.0f;
    #pragma unroll
    for (int yy = 0; yy < 4; yy++) {
        float acc = 0.0f;
        #pragma unroll
        for (int xx = 0; xx < 4; xx++)
            acc += wx[xx]*__ldg(qc + jy[yy]*160 + jx[xx]);
        s += wy[yy]*acc;
    }
    o[idx] = s;
}

// ---------------- 3x3 conv, 32->32, pad 1, dual image (gridDim.z) ------------
// tile 64x4; 256 threads; thread = 4 px x 8 co (4 co-groups) -> acc 16 u64.
// 3 blocks/SM (24 warps). Weights LDS.128 broadcast.
// MODE 0: relu(conv)   MODE 1: lrelu(conv + skip)
#define C3_CHUNK 16
#define C3_RS   68
#define C3_CIS  (6*C3_RS)               // 408 floats per ci (4 rows + 2 halo)
#define C3_SIN  (C3_CHUNK*C3_CIS)       // 6528 floats
#define C3_SW   (C3_CHUNK*9*32)         // 4608 floats
#define C3_SMEM ((C3_SIN + C3_SW)*4)    // 44544 B

template<int MODE>
__global__ void __launch_bounds__(256, 3) conv3_k(
    const float* __restrict__ in0, const float* __restrict__ in1,
    const float* __restrict__ wt,  const float* __restrict__ bs,
    const float* __restrict__ sk0, const float* __restrict__ sk1,
    float* __restrict__ out0, float* __restrict__ out1)
{
    extern __shared__ float sm[];
    float* s_in = sm;             // [ci][6][68 (66 used)]
    float* s_w  = sm + C3_SIN;    // [ci][9][32co]
    const float* in = blockIdx.z ? in1 : in0;
    const float* sk = blockIdx.z ? sk1 : sk0;
    float* out      = blockIdx.z ? out1 : out0;
    const int tid = threadIdx.x;
    const int txg = tid & 15;          // 16 x-groups (4 px each)
    const int ty  = (tid >> 4) & 3;    // 4 rows
    const int cog = tid >> 6;          // 4 channel groups (8 co each)
    const int ox0 = blockIdx.x*64, oy0 = blockIdx.y*4;

    u64 acc[4][4];
    #pragma unroll
    for (int cp = 0; cp < 4; cp++) {
        u64 b = pack2(__ldg(bs + cog*8 + 2*cp), __ldg(bs + cog*8 + 2*cp + 1));
        #pragma unroll
        for (int p = 0; p < 4; p++) acc[p][cp] = b;
    }

    for (int c0 = 0; c0 < 32; c0 += C3_CHUNK) {
        if (c0) __syncthreads();
        for (int i = tid; i < C3_CHUNK*6*66; i += 256) {
            int ci = i / 396, rem = i % 396;
            int r = rem / 66, cc = rem % 66;
            int y = oy0 - 1 + r, x = ox0 - 1 + cc;
            s_in[ci*C3_CIS + r*C3_RS + cc] =
                (y >= 0 && y < HH && x >= 0 && x < WW) ? in[(c0+ci)*HWSZ + y*WW + x] : 0.0f;
        }
        for (int i = tid; i < C3_SW; i += 256) {
            int ci = i / 288, rem = i % 288;
            int k = rem >> 5, co = rem & 31;
            s_w[i] = wt[(co*32 + c0 + ci)*9 + k];
        }
        __syncthreads();

        for (int ci = 0; ci < C3_CHUNK; ci++) {
            const float* base = s_in + ci*C3_CIS + ty*C3_RS + txg*4;
            const float* wb   = s_w + ci*288 + cog*8;
            #pragma unroll
            for (int ky = 0; ky < 3; ky++) {
                const float* rp = base + ky*C3_RS;
                float4 v4 = *(const float4*)rp;
                float2 v2 = *(const float2*)(rp + 4);
                u64 vp[6];
                vp[0]=pack2(v4.x,v4.x); vp[1]=pack2(v4.y,v4.y); vp[2]=pack2(v4.z,v4.z);
                vp[3]=pack2(v4.w,v4.w); vp[4]=pack2(v2.x,v2.x); vp[5]=pack2(v2.y,v2.y);
                #pragma unroll
                for (int kx = 0; kx < 3; kx++) {
                    const ulonglong2* wq = (const ulonglong2*)(wb + (ky*3 + kx)*32);
                    ulonglong2 w0 = wq[0], w1 = wq[1];
                    u64 w[4] = {w0.x, w0.y, w1.x, w1.y};
                    #pragma unroll
                    for (int p = 0; p < 4; p++)
                        #pragma unroll
                        for (int cp = 0; cp < 4; cp++)
                            acc[p][cp] = fma2(vp[p+kx], w[cp], acc[p][cp]);
                }
            }
        }
    }

    int o = (oy0 + ty)*WW + ox0 + txg*4;
    #pragma unroll
    for (int cp = 0; cp < 4; cp++) {
        int coe = cog*8 + 2*cp;
        float4 ve, vo;
        unpack2(acc[0][cp], ve.x, vo.x);
        unpack2(acc[1][cp], ve.y, vo.y);
        unpack2(acc[2][cp], ve.z, vo.z);
        unpack2(acc[3][cp], ve.w, vo.w);
        if (MODE == 0) {
            ve.x=fmaxf(ve.x,0.f); ve.y=fmaxf(ve.y,0.f); ve.z=fmaxf(ve.z,0.f); ve.w=fmaxf(ve.w,0.f);
            vo.x=fmaxf(vo.x,0.f); vo.y=fmaxf(vo.y,0.f); vo.z=fmaxf(vo.z,0.f); vo.w=fmaxf(vo.w,0.f);
        } else {
            float4 se = *(const float4*)(sk + coe*HWSZ + o);
            float4 so = *(const float4*)(sk + (coe+1)*HWSZ + o);
            ve.x+=se.x; ve.y+=se.y; ve.z+=se.z; ve.w+=se.w;
            vo.x+=so.x; vo.y+=so.y; vo.z+=so.z; vo.w+=so.w;
            ve.x=(ve.x>=0.f)?ve.x:0.2f*ve.x; ve.y=(ve.y>=0.f)?ve.y:0.2f*ve.y;
            ve.z=(ve.z>=0.f)?ve.z:0.2f*ve.z; ve.w=(ve.w>=0.f)?ve.w:0.2f*ve.w;
            vo.x=(vo.x>=0.f)?vo.x:0.2f*vo.x; vo.y=(vo.y>=0.f)?vo.y:0.2f*vo.y;
            vo.z=(vo.z>=0.f)?vo.z:0.2f*vo.z; vo.w=(vo.w>=0.f)?vo.w:0.2f*vo.w;
        }
        *(float4*)(out + coe*HWSZ + o)     = ve;
        *(float4*)(out + (coe+1)*HWSZ + o) = vo;
    }
}

// ---------------- 5x5 conv, CIN->32, pad 2, lrelu, dual image ----------------
// tile 64x4; thread = 4 px x 8 co; 3 blocks/SM
#define C5_RS  68
#define C5_CIS (8*C5_RS)    // 544 floats per ci (4 rows + 4 halo)

template<int CIN, int CHUNK>
__global__ void __launch_bounds__(256, 3) conv5_k(
    const float* __restrict__ in0, const float* __restrict__ in1,
    const float* __restrict__ wt,  const float* __restrict__ bs,
    float* __restrict__ out0, float* __restrict__ out1)
{
    extern __shared__ float sm[];
    float* s_in = sm;                   // [CHUNK][8][68]
    float* s_w  = sm + CHUNK*C5_CIS;    // [CHUNK][25][32co]
    const float* in = blockIdx.z ? in1 : in0;
    float* out      = blockIdx.z ? out1 : out0;
    const int tid = threadIdx.x;
    const int txg = tid & 15;
    const int ty  = (tid >> 4) & 3;
    const int cog = tid >> 6;
    const int ox0 = blockIdx.x*64, oy0 = blockIdx.y*4;

    u64 acc[4][4];
    #pragma unroll
    for (int cp = 0; cp < 4; cp++) {
        u64 b = pack2(__ldg(bs + cog*8 + 2*cp), __ldg(bs + cog*8 + 2*cp + 1));
        #pragma unroll
        for (int p = 0; p < 4; p++) acc[p][cp] = b;
    }

    for (int c0 = 0; c0 < CIN; c0 += CHUNK) {
        if (c0) __syncthreads();
        for (int i = tid; i < CHUNK*8*68; i += 256) {
            int ci = i / 544, rem = i % 544;
            int r = rem / 68, cc = rem % 68;
            int y = oy0 - 2 + r, x = ox0 - 2 + cc;
            s_in[i] = (y >= 0 && y < HH && x >= 0 && x < WW) ? in[(c0+ci)*HWSZ + y*WW + x] : 0.0f;
        }
        for (int i = tid; i < CHUNK*800; i += 256) {
            int ci = i / 800, rem = i % 800;
            int k = rem >> 5, co = rem & 31;
            s_w[i] = wt[(co*CIN + c0 + ci)*25 + k];
        }
        __syncthreads();

        for (int ci = 0; ci < CHUNK; ci++) {
            const float* base = s_in + ci*C5_CIS + ty*C5_RS + txg*4;
            const float* wb   = s_w + ci*800 + cog*8;
            #pragma unroll
            for (int ky = 0; ky < 5; ky++) {
                const float* rp = base + ky*C5_RS;
                float4 a4 = *(const float4*)rp;
                float4 b4 = *(const float4*)(rp + 4);
                u64 vp[8];
                vp[0]=pack2(a4.x,a4.x); vp[1]=pack2(a4.y,a4.y); vp[2]=pack2(a4.z,a4.z);
                vp[3]=pack2(a4.w,a4.w); vp[4]=pack2(b4.x,b4.x); vp[5]=pack2(b4.y,b4.y);
                vp[6]=pack2(b4.z,b4.z); vp[7]=pack2(b4.w,b4.w);
                #pragma unroll
                for (int kx = 0; kx < 5; kx++) {
                    const ulonglong2* wq = (const ulonglong2*)(wb + (ky*5 + kx)*32);
                    ulonglong2 w0 = wq[0], w1 = wq[1];
                    u64 w[4] = {w0.x, w0.y, w1.x, w1.y};
                    #pragma unroll
                    for (int p = 0; p < 4; p++)
                        #pragma unroll
                        for (int cp = 0; cp < 4; cp++)
                            acc[p][cp] = fma2(vp[p+kx], w[cp], acc[p][cp]);
                }
            }
        }
    }

    int o = (oy0 + ty)*WW + ox0 + txg*4;
    #pragma unroll
    for (int cp = 0; cp < 4; cp++) {
        int coe = cog*8 + 2*cp;
        float4 ve, vo;
        unpack2(acc[0][cp], ve.x, vo.x);
        unpack2(acc[1][cp], ve.y, vo.y);
        unpack2(acc[2][cp], ve.z, vo.z);
        unpack2(acc[3][cp], ve.w, vo.w);
        ve.x=(ve.x>=0.f)?ve.x:0.2f*ve.x; ve.y=(ve.y>=0.f)?ve.y:0.2f*ve.y;
        ve.z=(ve.z>=0.f)?ve.z:0.2f*ve.z; ve.w=(ve.w>=0.f)?ve.w:0.2f*ve.w;
        vo.x=(vo.x>=0.f)?vo.x:0.2f*vo.x; vo.y=(vo.y>=0.f)?vo.y:0.2f*vo.y;
        vo.z=(vo.z>=0.f)?vo.z:0.2f*vo.z; vo.w=(vo.w>=0.f)?vo.w:0.2f*vo.w;
        *(float4*)(out + coe*HWSZ + o)     = ve;
        *(float4*)(out + (coe+1)*HWSZ + o) = vo;
    }
}

// ---------------- fused 1x1 affine head + deformable 2x2 bilinear sampler ----
__device__ __forceinline__ int reflect_idx(int i) {  // xp coord -> x coord
    int r = i - 1;
    r = (r < 0) ? -r : r;
    r = (r > 319) ? (638 - r) : r;
    return r;
}

__global__ void sampler_k(const float* __restrict__ hid, const float* __restrict__ w2,
                          const float* __restrict__ b2, const float* __restrict__ x,
                          float* __restrict__ out) {
    __shared__ float s_w2[96];
    int tid = threadIdx.x;
    if (tid < 96) s_w2[tid] = w2[tid];
    __syncthreads();
    int p = blockIdx.x*256 + tid;                    // 102400 exact
    int h = p / WW, w = p % WW;

    float a0 = __ldg(b2 + 0), a1 = __ldg(b2 + 1), a2 = __ldg(b2 + 2);
    #pragma unroll 4
    for (int c = 0; c < 32; c++) {
        float hv = hid[c*HWSZ + p];
        a0 += hv*s_w2[c];
        a1 += hv*s_w2[32 + c];
        a2 += hv*s_w2[64 + c];
    }
    a0 = fminf(fmaxf(a0 + 1.0f, -3.0f), 3.0f);       // s_x
    a1 = fminf(fmaxf(a1 + 1.0f, -3.0f), 3.0f);       // s_y
    a2 = fminf(fmaxf(a2 + 1.0f, -3.0f), 3.0f);
    float th = (a2 - 1.0f)*1.0472f;
    float ct = cosf(th), st = sinf(th);

    int   idx[16];
    float wg[16];
    #pragma unroll
    for (int k = 0; k < 4; k++) {
        float pnx = (k & 2) ? 0.5f : -0.5f;
        float pny = (k & 1) ? 0.5f : -0.5f;
        float px = pnx*a0, py = pny*a1;
        float rx = px*ct - py*st;
        float ry = px*st + py*ct;
        float p_x = rx + 0.5f + (float)(h + 1);
        float p_y = ry + 0.5f + (float)(w + 1);
        float ltx = floorf(p_x), lty = floorf(p_y);
        float ltxc = fminf(fmaxf(ltx,        0.0f), 321.0f);
        float ltyc = fminf(fmaxf(lty,        0.0f), 321.0f);
        float rbxc = fminf(fmaxf(ltx + 1.0f, 0.0f), 321.0f);
        float rbyc = fminf(fmaxf(lty + 1.0f, 0.0f), 321.0f);
        float pxc  = fminf(fmaxf(p_x,        0.0f), 321.0f);
        float pyc  = fminf(fmaxf(p_y,        0.0f), 321.0f);
        float wlx = 1.0f + ltxc - pxc;
        float wrx = 1.0f - (rbxc - pxc);
        float wly = 1.0f + ltyc - pyc;
        float wry = 1.0f - (rbyc - pyc);
        int rl = reflect_idx((int)ltxc);
        int rr = reflect_idx((int)rbxc);
        int cl = reflect_idx((int)ltyc);
        int cr = reflect_idx((int)rbyc);
        idx[k*4+0] = rl*WW + cl;  wg[k*4+0] = wlx*wly;   // lt
        idx[k*4+1] = rr*WW + cr;  wg[k*4+1] = wrx*wry;   // rb
        idx[k*4+2] = rl*WW + cr;  wg[k*4+2] = wlx*wry;   // lb
        idx[k*4+3] = rr*WW + cl;  wg[k*4+3] = wrx*wly;   // rt
    }

    int ob = (2*h)*640 + 2*w;
    for (int c = 0; c < 64; c++) {
        const float* xc = x + c*HWSZ;
        float* oc = out + c*640*640;
        float v[4];
        #pragma unroll
        for (int k = 0; k < 4; k++) {
            v[k] = wg[k*4+0]*__ldg(xc + idx[k*4+0])
                 + wg[k*4+1]*__ldg(xc + idx[k*4+1])
                 + wg[k*4+2]*__ldg(xc + idx[k*4+2])
                 + wg[k*4+3]*__ldg(xc + idx[k*4+3]);
        }
        *(float2*)(oc + ob)       = make_float2(v[0], v[1]);
        *(float2*)(oc + ob + 640) = make_float2(v[2], v[3]);
    }
}

// ---------------- launch ------------------------------------------------------
extern "C" void kernel_launch(void* const* d_in, const int* in_sizes, int n_in,
                              void* d_out, int out_size) {
    const float* x    = (const float*)d_in[0];
    const float* qry  = (const float*)d_in[1];
    const float* ref  = (const float*)d_in[2];
    const float* c1w  = (const float*)d_in[3];
    const float* c1b  = (const float*)d_in[4];
    const float* r1w1 = (const float*)d_in[5];
    const float* r1b1 = (const float*)d_in[6];
    const float* r1w2 = (const float*)d_in[7];
    const float* r1b2 = (const float*)d_in[8];
    const float* p1w  = (const float*)d_in[9];
    const float* p1b  = (const float*)d_in[10];
    const float* prw1 = (const float*)d_in[11];
    const float* prb1 = (const float*)d_in[12];
    const float* prw2 = (const float*)d_in[13];
    const float* prb2 = (const float*)d_in[14];
    const float* p2w  = (const float*)d_in[15];
    const float* p2b  = (const float*)d_in[16];
    float* out = (float*)d_out;

    float *up, *feat, *buf1, *buf2, *hid;
    cudaGetSymbolAddress((void**)&up,   g_up);
    cudaGetSymbolAddress((void**)&feat, g_feat);
    cudaGetSymbolAddress((void**)&buf1, g_buf1);
    cudaGetSymbolAddress((void**)&buf2, g_buf2);
    cudaGetSymbolAddress((void**)&hid,  g_hid);

    const int SM3    = C3_SMEM;                         // 44544 B
    const int SM5_3  = (3*C5_CIS + 3*800)*4;            // 16128 B
    const int SM5_64 = (8*C5_CIS + 8*800)*4;            // 43008 B
    cudaFuncSetAttribute(conv3_k<0>, cudaFuncAttributeMaxDynamicSharedMemorySize, SM3);
    cudaFuncSetAttribute(conv3_k<1>, cudaFuncAttributeMaxDynamicSharedMemorySize, SM3);
    cudaFuncSetAttribute(conv5_k<3,3>,  cudaFuncAttributeMaxDynamicSharedMemorySize, SM5_3);
    cudaFuncSetAttribute(conv5_k<64,8>, cudaFuncAttributeMaxDynamicSharedMemorySize, SM5_64);

    dim3 cg2(5, 80, 2);   // 64x4 tiles, dual image
    dim3 cg1(5, 80, 1);

    // 1. bicubic upsample query 160->320
    bicubic_k<<<(3*HWSZ)/256, 256>>>(qry, up);

    // 2+3. both feature heads batched over gridDim.z
    conv5_k<3,3><<<cg2, 256, SM5_3>>>(ref, up, c1w, c1b, buf1, buf1 + 32*HWSZ);
    conv3_k<0><<<cg2, 256, SM3>>>(buf1, buf1 + 32*HWSZ, r1w1, r1b1,
                                  nullptr, nullptr, buf2, buf2 + 32*HWSZ);
    conv3_k<1><<<cg2, 256, SM3>>>(buf2, buf2 + 32*HWSZ, r1w2, r1b2,
                                  buf1, buf1 + 32*HWSZ, feat, feat + 32*HWSZ);

    // 4. fusion head
    conv5_k<64,8><<<cg1, 256, SM5_64>>>(feat, feat, p1w, p1b, buf1, buf1);
    conv3_k<0><<<cg1, 256, SM3>>>(buf1, buf1, prw1, prb1, nullptr, nullptr, buf2, buf2);
    conv3_k<1><<<cg1, 256, SM3>>>(buf2, buf2, prw2, prb2, buf1, buf1, hid, hid);

    // 5. fused 1x1 affine head + deformable sampler -> out (64,640,640)
    sampler_k<<<HWSZ/256, 256>>>(hid, p2w, p2b, x, out);
}

// round 8
// speedup vs baseline: 1.1778x; 1.0590x over previous
#include <cuda_runtime.h>
#include <math.h>

#define HH 320
#define WW 320
#define HWSZ (320*320)

// ---------------- scratch (static device globals; no allocation) -------------
__device__ float g_up[3*HWSZ];      // bicubic-upsampled query
__device__ float g_feat[64*HWSZ];   // [rf(0..31) | qf(32..63)]
__device__ float g_buf1[64*HWSZ];   // 2 images x 32 ch
__device__ float g_buf2[64*HWSZ];
__device__ float g_hid[32*HWSZ];

typedef unsigned long long u64;

// ---------------- packed f32x2 helpers (sm_103a FFMA2) -----------------------
__device__ __forceinline__ u64 pack2(float a, float b) {
    u64 r; asm("mov.b64 %0,{%1,%2};" : "=l"(r) : "f"(a), "f"(b)); return r;
}
__device__ __forceinline__ void unpack2(u64 v, float& a, float& b) {
    asm("mov.b64 {%0,%1},%2;" : "=f"(a), "=f"(b) : "l"(v));
}
__device__ __forceinline__ u64 fma2(u64 a, u64 b, u64 c) {
    u64 d; asm("fma.rn.f32x2 %0,%1,%2,%3;" : "=l"(d) : "l"(a), "l"(b), "l"(c)); return d;
}

// ---------------- bicubic x2 (A = -0.75) -------------------------------------
__device__ __forceinline__ float cubicw(float t) {
    t = fabsf(t);
    if (t <= 1.0f) return ((1.25f*t - 2.25f)*t)*t + 1.0f;
    if (t <  2.0f) return -0.75f*((((t - 5.0f)*t + 8.0f)*t) - 4.0f);
    return 0.0f;
}

__global__ void bicubic_k(const float* __restrict__ q, float* __restrict__ o) {
    int idx = blockIdx.x*256 + threadIdx.x;            // 3*320*320 exact
    int ox = idx % 320;
    int t  = idx / 320;
    int oy = t % 320;
    int c  = t / 320;
    float sy = (oy + 0.5f)*0.5f - 0.5f;
    float sx = (ox + 0.5f)*0.5f - 0.5f;
    int iy0 = (int)floorf(sy), ix0 = (int)floorf(sx);
    float wy[4], wx[4]; int jy[4], jx[4];
    #pragma unroll
    for (int k = 0; k < 4; k++) {
        int ty = iy0 - 1 + k;
        wy[k] = cubicw(sy - (float)ty);
        jy[k] = min(max(ty, 0), 159);
        int tx = ix0 - 1 + k;
        wx[k] = cubicw(sx - (float)tx);
        jx[k] = min(max(tx, 0), 159);
    }
    const float* qc = q + c*160*160;
    float s = 0.0f;
    #pragma unroll
    for (int yy = 0; yy < 4; yy++) {
        float acc = 0.0f;
        #pragma unroll
        for (int xx = 0; xx < 4; xx++)
            acc += wx[xx]*__ldg(qc + jy[yy]*160 + jx[xx]);
        s += wy[yy]*acc;
    }
    o[idx] = s;
}

// ---------------- 3x3 conv, 32->32, pad 1, dual image (gridDim.z) ------------
// tile 64x4; 256 threads; thread = 4 px x 8 co (4 co-groups).
// Staging addressing hoisted: div/mod once, pointer increments per ci.
// MODE 0: relu(conv)   MODE 1: lrelu(conv + skip)
#define C3_CHUNK 16
#define C3_RS   68
#define C3_CIS  (6*C3_RS)               // 408 floats per ci
#define C3_SIN  (C3_CHUNK*C3_CIS)       // 6528 floats
#define C3_SW   (C3_CHUNK*9*32)         // 4608 floats
#define C3_SMEM ((C3_SIN + C3_SW)*4)    // 44544 B

template<int MODE>
__global__ void __launch_bounds__(256, 3) conv3_k(
    const float* __restrict__ in0, const float* __restrict__ in1,
    const float* __restrict__ wt,  const float* __restrict__ bs,
    const float* __restrict__ sk0, const float* __restrict__ sk1,
    float* __restrict__ out0, float* __restrict__ out1)
{
    extern __shared__ float sm[];
    float* s_in = sm;             // [ci][6][68 (66 used)]
    float* s_w  = sm + C3_SIN;    // [ci][9][32co]
    const float* in = blockIdx.z ? in1 : in0;
    const float* sk = blockIdx.z ? sk1 : sk0;
    float* out      = blockIdx.z ? out1 : out0;
    const int tid = threadIdx.x;
    const int txg = tid & 15;
    const int ty  = (tid >> 4) & 3;
    const int cog = tid >> 6;
    const int ox0 = blockIdx.x*64, oy0 = blockIdx.y*4;

    // ---- hoisted staging maps (computed once) ----
    // input: per ci 396 elements (6 rows x 66 cols); thread handles tid, tid+256
    const int r1 = tid / 66,        c1 = tid % 66;
    const int r2 = (tid+256) / 66,  c2 = (tid+256) % 66;
    const bool has2 = (tid + 256) < 396;
    const int y1 = oy0 - 1 + r1, x1 = ox0 - 1 + c1;
    const int y2 = oy0 - 1 + r2, x2 = ox0 - 1 + c2;
    const bool ok1 = (y1 >= 0 && y1 < HH && x1 >= 0 && x1 < WW);
    const bool ok2 = has2 && (y2 >= 0 && y2 < HH && x2 >= 0 && x2 < WW);
    const int g1 = ok1 ? (y1*WW + x1) : 0;
    const int g2 = ok2 ? (y2*WW + x2) : 0;
    const int so1 = r1*C3_RS + c1;
    const int so2 = r2*C3_RS + c2;
    // weights: per ci 288 elements (9k x 32co); thread handles tid, tid+256 (tid<32)
    const int wk1 = tid >> 5, wco1 = tid & 31;
    const int wg1 = (wco1*32)*9 + wk1;              // + (c0+ci)*9
    const int ws1 = wk1*32 + wco1;
    const bool wh2 = tid < 32;                      // k=8, co=tid
    const int wg2 = (tid*32)*9 + 8;
    const int ws2 = 8*32 + tid;

    u64 acc[4][4];
    #pragma unroll
    for (int cp = 0; cp < 4; cp++) {
        u64 b = pack2(__ldg(bs + cog*8 + 2*cp), __ldg(bs + cog*8 + 2*cp + 1));
        #pragma unroll
        for (int p = 0; p < 4; p++) acc[p][cp] = b;
    }

    for (int c0 = 0; c0 < 32; c0 += C3_CHUNK) {
        if (c0) __syncthreads();
        {
            const float* ip1 = in + c0*HWSZ + g1;
            const float* ip2 = in + c0*HWSZ + g2;
            float* sp1 = s_in + so1;
            float* sp2 = s_in + so2;
            #pragma unroll 4
            for (int ci = 0; ci < C3_CHUNK; ci++) {
                sp1[ci*C3_CIS] = ok1 ? ip1[ci*HWSZ] : 0.0f;
                if (has2) sp2[ci*C3_CIS] = ok2 ? ip2[ci*HWSZ] : 0.0f;
            }
            const float* wp1 = wt + wg1 + c0*9;
            float* sw1 = s_w + ws1;
            #pragma unroll 4
            for (int ci = 0; ci < C3_CHUNK; ci++)
                sw1[ci*288] = wp1[ci*9];
            if (wh2) {
                const float* wp2 = wt + wg2 + c0*9;
                float* sw2 = s_w + ws2;
                #pragma unroll 4
                for (int ci = 0; ci < C3_CHUNK; ci++)
                    sw2[ci*288] = wp2[ci*9];
            }
        }
        __syncthreads();

        for (int ci = 0; ci < C3_CHUNK; ci++) {
            const float* base = s_in + ci*C3_CIS + ty*C3_RS + txg*4;
            const float* wb   = s_w + ci*288 + cog*8;
            #pragma unroll
            for (int ky = 0; ky < 3; ky++) {
                const float* rp = base + ky*C3_RS;
                float4 v4 = *(const float4*)rp;
                float2 v2 = *(const float2*)(rp + 4);
                u64 vp[6];
                vp[0]=pack2(v4.x,v4.x); vp[1]=pack2(v4.y,v4.y); vp[2]=pack2(v4.z,v4.z);
                vp[3]=pack2(v4.w,v4.w); vp[4]=pack2(v2.x,v2.x); vp[5]=pack2(v2.y,v2.y);
                #pragma unroll
                for (int kx = 0; kx < 3; kx++) {
                    const ulonglong2* wq = (const ulonglong2*)(wb + (ky*3 + kx)*32);
                    ulonglong2 w0 = wq[0], w1 = wq[1];
                    u64 w[4] = {w0.x, w0.y, w1.x, w1.y};
                    #pragma unroll
                    for (int p = 0; p < 4; p++)
                        #pragma unroll
                        for (int cp = 0; cp < 4; cp++)
                            acc[p][cp] = fma2(vp[p+kx], w[cp], acc[p][cp]);
                }
            }
        }
    }

    int o = (oy0 + ty)*WW + ox0 + txg*4;
    #pragma unroll
    for (int cp = 0; cp < 4; cp++) {
        int coe = cog*8 + 2*cp;
        float4 ve, vo;
        unpack2(acc[0][cp], ve.x, vo.x);
        unpack2(acc[1][cp], ve.y, vo.y);
        unpack2(acc[2][cp], ve.z, vo.z);
        unpack2(acc[3][cp], ve.w, vo.w);
        if (MODE == 0) {
            ve.x=fmaxf(ve.x,0.f); ve.y=fmaxf(ve.y,0.f); ve.z=fmaxf(ve.z,0.f); ve.w=fmaxf(ve.w,0.f);
            vo.x=fmaxf(vo.x,0.f); vo.y=fmaxf(vo.y,0.f); vo.z=fmaxf(vo.z,0.f); vo.w=fmaxf(vo.w,0.f);
        } else {
            float4 se = *(const float4*)(sk + coe*HWSZ + o);
            float4 so = *(const float4*)(sk + (coe+1)*HWSZ + o);
            ve.x+=se.x; ve.y+=se.y; ve.z+=se.z; ve.w+=se.w;
            vo.x+=so.x; vo.y+=so.y; vo.z+=so.z; vo.w+=so.w;
            ve.x=(ve.x>=0.f)?ve.x:0.2f*ve.x; ve.y=(ve.y>=0.f)?ve.y:0.2f*ve.y;
            ve.z=(ve.z>=0.f)?ve.z:0.2f*ve.z; ve.w=(ve.w>=0.f)?ve.w:0.2f*ve.w;
            vo.x=(vo.x>=0.f)?vo.x:0.2f*vo.x; vo.y=(vo.y>=0.f)?vo.y:0.2f*vo.y;
            vo.z=(vo.z>=0.f)?vo.z:0.2f*vo.z; vo.w=(vo.w>=0.f)?vo.w:0.2f*vo.w;
        }
        *(float4*)(out + coe*HWSZ + o)     = ve;
        *(float4*)(out + (coe+1)*HWSZ + o) = vo;
    }
}

// ---------------- 5x5 conv, CIN->32, pad 2, lrelu, dual image ----------------
// tile 64x4; thread = 4 px x 8 co; hoisted staging addressing
#define C5_RS  68
#define C5_CIS (8*C5_RS)    // 544 floats per ci

template<int CIN, int CHUNK>
__global__ void __launch_bounds__(256, 3) conv5_k(
    const float* __restrict__ in0, const float* __restrict__ in1,
    const float* __restrict__ wt,  const float* __restrict__ bs,
    float* __restrict__ out0, float* __restrict__ out1)
{
    extern __shared__ float sm[];
    float* s_in = sm;                   // [CHUNK][8][68]
    float* s_w  = sm + CHUNK*C5_CIS;    // [CHUNK][25][32co]
    const float* in = blockIdx.z ? in1 : in0;
    float* out      = blockIdx.z ? out1 : out0;
    const int tid = threadIdx.x;
    const int txg = tid & 15;
    const int ty  = (tid >> 4) & 3;
    const int cog = tid >> 6;
    const int ox0 = blockIdx.x*64, oy0 = blockIdx.y*4;

    // input: per ci 544 elements (8 rows x 68 cols); thread: tid, tid+256, tid+512(tid<32)
    const int ir[3] = { tid/68, (tid+256)/68, (tid+512)/68 };
    const int ic[3] = { tid%68, (tid+256)%68, (tid+512)%68 };
    const bool ihas[3] = { true, true, tid < 32 };
    bool iok[3]; int ig[3], iso[3];
    #pragma unroll
    for (int j = 0; j < 3; j++) {
        int y = oy0 - 2 + ir[j], x = ox0 - 2 + ic[j];
        iok[j] = ihas[j] && (y >= 0 && y < HH && x >= 0 && x < WW);
        ig[j]  = iok[j] ? (y*WW + x) : 0;
        iso[j] = ir[j]*C5_RS + ic[j];
    }
    // weights: per ci 800 elements (25k x 32co); thread: tid, +256, +512, +768(tid<32)
    int wk[4], wco[4]; bool whas[4];
    #pragma unroll
    for (int j = 0; j < 4; j++) {
        int e = tid + j*256;
        wk[j] = e >> 5; wco[j] = e & 31;
        whas[j] = e < 800;
    }

    u64 acc[4][4];
    #pragma unroll
    for (int cp = 0; cp < 4; cp++) {
        u64 b = pack2(__ldg(bs + cog*8 + 2*cp), __ldg(bs + cog*8 + 2*cp + 1));
        #pragma unroll
        for (int p = 0; p < 4; p++) acc[p][cp] = b;
    }

    for (int c0 = 0; c0 < CIN; c0 += CHUNK) {
        if (c0) __syncthreads();
        #pragma unroll
        for (int j = 0; j < 3; j++) {
            if (!ihas[j]) continue;
            const float* ip = in + c0*HWSZ + ig[j];
            float* sp = s_in + iso[j];
            #pragma unroll 4
            for (int ci = 0; ci < CHUNK; ci++)
                sp[ci*C5_CIS] = iok[j] ? ip[ci*HWSZ] : 0.0f;
        }
        #pragma unroll
        for (int j = 0; j < 4; j++) {
            if (!whas[j]) continue;
            const float* wp = wt + (wco[j]*CIN + c0)*25 + wk[j];
            float* sw = s_w + wk[j]*32 + wco[j];
            #pragma unroll 4
            for (int ci = 0; ci < CHUNK; ci++)
                sw[ci*800] = wp[ci*25];
        }
        __syncthreads();

        for (int ci = 0; ci < CHUNK; ci++) {
            const float* base = s_in + ci*C5_CIS + ty*C5_RS + txg*4;
            const float* wb   = s_w + ci*800 + cog*8;
            #pragma unroll
            for (int ky = 0; ky < 5; ky++) {
                const float* rp = base + ky*C5_RS;
                float4 a4 = *(const float4*)rp;
                float4 b4 = *(const float4*)(rp + 4);
                u64 vp[8];
                vp[0]=pack2(a4.x,a4.x); vp[1]=pack2(a4.y,a4.y); vp[2]=pack2(a4.z,a4.z);
                vp[3]=pack2(a4.w,a4.w); vp[4]=pack2(b4.x,b4.x); vp[5]=pack2(b4.y,b4.y);
                vp[6]=pack2(b4.z,b4.z); vp[7]=pack2(b4.w,b4.w);
                #pragma unroll
                for (int kx = 0; kx < 5; kx++) {
                    const ulonglong2* wq = (const ulonglong2*)(wb + (ky*5 + kx)*32);
                    ulonglong2 w0 = wq[0], w1 = wq[1];
                    u64 w[4] = {w0.x, w0.y, w1.x, w1.y};
                    #pragma unroll
                    for (int p = 0; p < 4; p++)
                        #pragma unroll
                        for (int cp = 0; cp < 4; cp++)
                            acc[p][cp] = fma2(vp[p+kx], w[cp], acc[p][cp]);
                }
            }
        }
    }

    int o = (oy0 + ty)*WW + ox0 + txg*4;
    #pragma unroll
    for (int cp = 0; cp < 4; cp++) {
        int coe = cog*8 + 2*cp;
        float4 ve, vo;
        unpack2(acc[0][cp], ve.x, vo.x);
        unpack2(acc[1][cp], ve.y, vo.y);
        unpack2(acc[2][cp], ve.z, vo.z);
        unpack2(acc[3][cp], ve.w, vo.w);
        ve.x=(ve.x>=0.f)?ve.x:0.2f*ve.x; ve.y=(ve.y>=0.f)?ve.y:0.2f*ve.y;
        ve.z=(ve.z>=0.f)?ve.z:0.2f*ve.z; ve.w=(ve.w>=0.f)?ve.w:0.2f*ve.w;
        vo.x=(vo.x>=0.f)?vo.x:0.2f*vo.x; vo.y=(vo.y>=0.f)?vo.y:0.2f*vo.y;
        vo.z=(vo.z>=0.f)?vo.z:0.2f*vo.z; vo.w=(vo.w>=0.f)?vo.w:0.2f*vo.w;
        *(float4*)(out + coe*HWSZ + o)     = ve;
        *(float4*)(out + (coe+1)*HWSZ + o) = vo;
    }
}

// ---------------- fused 1x1 affine head + deformable 2x2 bilinear sampler ----
__device__ __forceinline__ int reflect_idx(int i) {  // xp coord -> x coord
    int r = i - 1;
    r = (r < 0) ? -r : r;
    r = (r > 319) ? (638 - r) : r;
    return r;
}

__global__ void sampler_k(const float* __restrict__ hid, const float* __restrict__ w2,
                          const float* __restrict__ b2, const float* __restrict__ x,
                          float* __restrict__ out) {
    __shared__ float s_w2[96];
    int tid = threadIdx.x;
    if (tid < 96) s_w2[tid] = w2[tid];
    __syncthreads();
    int p = blockIdx.x*256 + tid;                    // 102400 exact
    int h = p / WW, w = p % WW;

    float a0 = __ldg(b2 + 0), a1 = __ldg(b2 + 1), a2 = __ldg(b2 + 2);
    #pragma unroll 4
    for (int c = 0; c < 32; c++) {
        float hv = hid[c*HWSZ + p];
        a0 += hv*s_w2[c];
        a1 += hv*s_w2[32 + c];
        a2 += hv*s_w2[64 + c];
    }
    a0 = fminf(fmaxf(a0 + 1.0f, -3.0f), 3.0f);
    a1 = fminf(fmaxf(a1 + 1.0f, -3.0f), 3.0f);
    a2 = fminf(fmaxf(a2 + 1.0f, -3.0f), 3.0f);
    float th = (a2 - 1.0f)*1.0472f;
    float ct = cosf(th), st = sinf(th);

    int   idx[16];
    float wg[16];
    #pragma unroll
    for (int k = 0; k < 4; k++) {
        float pnx = (k & 2) ? 0.5f : -0.5f;
        float pny = (k & 1) ? 0.5f : -0.5f;
        float px = pnx*a0, py = pny*a1;
        float rx = px*ct - py*st;
        float ry = px*st + py*ct;
        float p_x = rx + 0.5f + (float)(h + 1);
        float p_y = ry + 0.5f + (float)(w + 1);
        float ltx = floorf(p_x), lty = floorf(p_y);
        float ltxc = fminf(fmaxf(ltx,        0.0f), 321.0f);
        float ltyc = fminf(fmaxf(lty,        0.0f), 321.0f);
        float rbxc = fminf(fmaxf(ltx + 1.0f, 0.0f), 321.0f);
        float rbyc = fminf(fmaxf(lty + 1.0f, 0.0f), 321.0f);
        float pxc  = fminf(fmaxf(p_x,        0.0f), 321.0f);
        float pyc  = fminf(fmaxf(p_y,        0.0f), 321.0f);
        float wlx = 1.0f + ltxc - pxc;
        float wrx = 1.0f - (rbxc - pxc);
        float wly = 1.0f + ltyc - pyc;
        float wry = 1.0f - (rbyc - pyc);
        int rl = reflect_idx((int)ltxc);
        int rr = reflect_idx((int)rbxc);
        int cl = reflect_idx((int)ltyc);
        int cr = reflect_idx((int)rbyc);
        idx[k*4+0] = rl*WW + cl;  wg[k*4+0] = wlx*wly;
        idx[k*4+1] = rr*WW + cr;  wg[k*4+1] = wrx*wry;
        idx[k*4+2] = rl*WW + cr;  wg[k*4+2] = wlx*wry;
        idx[k*4+3] = rr*WW + cl;  wg[k*4+3] = wrx*wly;
    }

    int ob = (2*h)*640 + 2*w;
    for (int c = 0; c < 64; c++) {
        const float* xc = x + c*HWSZ;
        float* oc = out + c*640*640;
        float v[4];
        #pragma unroll
        for (int k = 0; k < 4; k++) {
            v[k] = wg[k*4+0]*__ldg(xc + idx[k*4+0])
                 + wg[k*4+1]*__ldg(xc + idx[k*4+1])
                 + wg[k*4+2]*__ldg(xc + idx[k*4+2])
                 + wg[k*4+3]*__ldg(xc + idx[k*4+3]);
        }
        *(float2*)(oc + ob)       = make_float2(v[0], v[1]);
        *(float2*)(oc + ob + 640) = make_float2(v[2], v[3]);
    }
}

// ---------------- launch ------------------------------------------------------
extern "C" void kernel_launch(void* const* d_in, const int* in_sizes, int n_in,
                              void* d_out, int out_size) {
    const float* x    = (const float*)d_in[0];
    const float* qry  = (const float*)d_in[1];
    const float* ref  = (const float*)d_in[2];
    const float* c1w  = (const float*)d_in[3];
    const float* c1b  = (const float*)d_in[4];
    const float* r1w1 = (const float*)d_in[5];
    const float* r1b1 = (const float*)d_in[6];
    const float* r1w2 = (const float*)d_in[7];
    const float* r1b2 = (const float*)d_in[8];
    const float* p1w  = (const float*)d_in[9];
    const float* p1b  = (const float*)d_in[10];
    const float* prw1 = (const float*)d_in[11];
    const float* prb1 = (const float*)d_in[12];
    const float* prw2 = (const float*)d_in[13];
    const float* prb2 = (const float*)d_in[14];
    const float* p2w  = (const float*)d_in[15];
    const float* p2b  = (const float*)d_in[16];
    float* out = (float*)d_out;

    float *up, *feat, *buf1, *buf2, *hid;
    cudaGetSymbolAddress((void**)&up,   g_up);
    cudaGetSymbolAddress((void**)&feat, g_feat);
    cudaGetSymbolAddress((void**)&buf1, g_buf1);
    cudaGetSymbolAddress((void**)&buf2, g_buf2);
    cudaGetSymbolAddress((void**)&hid,  g_hid);

    const int SM3    = C3_SMEM;                         // 44544 B
    const int SM5_3  = (3*C5_CIS + 3*800)*4;            // 16128 B
    const int SM5_64 = (8*C5_CIS + 8*800)*4;            // 43008 B
    cudaFuncSetAttribute(conv3_k<0>, cudaFuncAttributeMaxDynamicSharedMemorySize, SM3);
    cudaFuncSetAttribute(conv3_k<1>, cudaFuncAttributeMaxDynamicSharedMemorySize, SM3);
    cudaFuncSetAttribute(conv5_k<3,3>,  cudaFuncAttributeMaxDynamicSharedMemorySize, SM5_3);
    cudaFuncSetAttribute(conv5_k<64,8>, cudaFuncAttributeMaxDynamicSharedMemorySize, SM5_64);

    dim3 cg2(5, 80, 2);   // 64x4 tiles, dual image
    dim3 cg1(5, 80, 1);

    // 1. bicubic upsample query 160->320
    bicubic_k<<<(3*HWSZ)/256, 256>>>(qry, up);

    // 2+3. both feature heads batched over gridDim.z
    conv5_k<3,3><<<cg2, 256, SM5_3>>>(ref, up, c1w, c1b, buf1, buf1 + 32*HWSZ);
    conv3_k<0><<<cg2, 256, SM3>>>(buf1, buf1 + 32*HWSZ, r1w1, r1b1,
                                  nullptr, nullptr, buf2, buf2 + 32*HWSZ);
    conv3_k<1><<<cg2, 256, SM3>>>(buf2, buf2 + 32*HWSZ, r1w2, r1b2,
                                  buf1, buf1 + 32*HWSZ, feat, feat + 32*HWSZ);

    // 4. fusion head
    conv5_k<64,8><<<cg1, 256, SM5_64>>>(feat, feat, p1w, p1b, buf1, buf1);
    conv3_k<0><<<cg1, 256, SM3>>>(buf1, buf1, prw1, prb1, nullptr, nullptr, buf2, buf2);
    conv3_k<1><<<cg1, 256, SM3>>>(buf2, buf2, prw2, prb2, buf1, buf1, hid, hid);

    // 5. fused 1x1 affine head + deformable sampler -> out (64,640,640)
    sampler_k<<<HWSZ/256, 256>>>(hid, p2w, p2b, x, out);
}

// round 9
// speedup vs baseline: 1.2485x; 1.0600x over previous
#include <cuda_runtime.h>
#include <math.h>
#include <stdint.h>

#define HH 320
#define WW 320
#define HWSZ (320*320)

// ---------------- scratch (static device globals; no allocation) -------------
__device__ float g_up[3*HWSZ];
__device__ float g_feat[64*HWSZ];
__device__ float g_buf1[64*HWSZ];
__device__ float g_buf2[64*HWSZ];
__device__ float g_hid[32*HWSZ];

typedef unsigned long long u64;

// ---------------- packed f32x2 helpers (sm_103a FFMA2) -----------------------
__device__ __forceinline__ u64 pack2(float a, float b) {
    u64 r; asm("mov.b64 %0,{%1,%2};" : "=l"(r) : "f"(a), "f"(b)); return r;
}
__device__ __forceinline__ void unpack2(u64 v, float& a, float& b) {
    asm("mov.b64 {%0,%1},%2;" : "=f"(a), "=f"(b) : "l"(v));
}
__device__ __forceinline__ u64 fma2(u64 a, u64 b, u64 c) {
    u64 d; asm("fma.rn.f32x2 %0,%1,%2,%3;" : "=l"(d) : "l"(a), "l"(b), "l"(c)); return d;
}

// ---------------- cp.async helpers -------------------------------------------
__device__ __forceinline__ void cp4(uint32_t s, const float* g, bool ok) {
    int sz = ok ? 4 : 0;
    asm volatile("cp.async.ca.shared.global [%0], [%1], 4, %2;"
                 :: "r"(s), "l"(g), "r"(sz) : "memory");
}
#define CP_COMMIT() asm volatile("cp.async.commit_group;" ::: "memory")
#define CP_WAIT(n)  asm volatile("cp.async.wait_group %0;" :: "n"(n) : "memory")

// ---------------- bicubic x2 (A = -0.75) -------------------------------------
__device__ __forceinline__ float cubicw(float t) {
    t = fabsf(t);
    if (t <= 1.0f) return ((1.25f*t - 2.25f)*t)*t + 1.0f;
    if (t <  2.0f) return -0.75f*((((t - 5.0f)*t + 8.0f)*t) - 4.0f);
    return 0.0f;
}

__global__ void bicubic_k(const float* __restrict__ q, float* __restrict__ o) {
    int idx = blockIdx.x*256 + threadIdx.x;
    int ox = idx % 320;
    int t  = idx / 320;
    int oy = t % 320;
    int c  = t / 320;
    float sy = (oy + 0.5f)*0.5f - 0.5f;
    float sx = (ox + 0.5f)*0.5f - 0.5f;
    int iy0 = (int)floorf(sy), ix0 = (int)floorf(sx);
    float wy[4], wx[4]; int jy[4], jx[4];
    #pragma unroll
    for (int k = 0; k < 4; k++) {
        int ty = iy0 - 1 + k;
        wy[k] = cubicw(sy - (float)ty);
        jy[k] = min(max(ty, 0), 159);
        int tx = ix0 - 1 + k;
        wx[k] = cubicw(sx - (float)tx);
        jx[k] = min(max(tx, 0), 159);
    }
    const float* qc = q + c*160*160;
    float s = 0.0f;
    #pragma unroll
    for (int yy = 0; yy < 4; yy++) {
        float acc = 0.0f;
        #pragma unroll
        for (int xx = 0; xx < 4; xx++)
            acc += wx[xx]*__ldg(qc + jy[yy]*160 + jx[xx]);
        s += wy[yy]*acc;
    }
    o[idx] = s;
}

// ---------------- 3x3 conv, 32->32, pad 1, dual image ------------------------
// tile 64x4; thread = 4 px x 8 co; cp.async double-buffered staging, CHUNK=8
#define C3_CHUNK 8
#define C3_RS   68
#define C3_CIS  (6*C3_RS)                    // 408
#define C3_BIN  (C3_CHUNK*C3_CIS)            // 3264
#define C3_BW   (C3_CHUNK*288)               // 2304
#define C3_BUF  (C3_BIN + C3_BW)             // 5568 floats
#define C3_SMEM (2*C3_BUF*4)                 // 44544 B

template<int MODE>
__global__ void __launch_bounds__(256, 3) conv3_k(
    const float* __restrict__ in0, const float* __restrict__ in1,
    const float* __restrict__ wt,  const float* __restrict__ bs,
    const float* __restrict__ sk0, const float* __restrict__ sk1,
    float* __restrict__ out0, float* __restrict__ out1)
{
    extern __shared__ float sm[];
    const uint32_t smem0 = (uint32_t)__cvta_generic_to_shared(sm);
    const float* in = blockIdx.z ? in1 : in0;
    const float* sk = blockIdx.z ? sk1 : sk0;
    float* out      = blockIdx.z ? out1 : out0;
    const int tid = threadIdx.x;
    const int txg = tid & 15;
    const int ty  = (tid >> 4) & 3;
    const int cog = tid >> 6;
    const int ox0 = blockIdx.x*64, oy0 = blockIdx.y*4;

    // hoisted staging maps: input per ci = 396 elems (6x66), slots tid, tid+256
    const int r1 = tid / 66,        c1 = tid % 66;
    const int r2 = (tid+256) / 66,  c2 = (tid+256) % 66;
    const bool has2 = tid < 140;
    const int y1 = oy0 - 1 + r1, x1 = ox0 - 1 + c1;
    const int y2 = oy0 - 1 + r2, x2 = ox0 - 1 + c2;
    const bool ok1 = (y1 >= 0 && y1 < HH && x1 >= 0 && x1 < WW);
    const bool ok2 = has2 && (y2 >= 0 && y2 < HH && x2 >= 0 && x2 < WW);
    const int g1 = ok1 ? (y1*WW + x1) : 0;
    const int g2 = ok2 ? (y2*WW + x2) : 0;
    const int so1 = r1*C3_RS + c1;
    const int so2 = r2*C3_RS + c2;
    // weights per ci = 288 elems (9k x 32co): slots tid, tid+256 (tid<32)
    const int wk1 = tid >> 5, wco1 = tid & 31;
    const int wgo1 = wco1*288 + wk1;             // + (c0+ci)*9
    const int wso1 = wk1*32 + wco1;
    const bool wh2 = tid < 32;
    const int wgo2 = tid*288 + 8;
    const int wso2 = 8*32 + tid;

    auto stage = [&](int nb, int c0) {
        uint32_t sb = smem0 + nb*(C3_BUF*4);
        const float* ip1 = in + c0*HWSZ + g1;
        uint32_t d1 = sb + so1*4;
        #pragma unroll
        for (int ci = 0; ci < C3_CHUNK; ci++)
            cp4(d1 + ci*(C3_CIS*4), ip1 + ci*HWSZ, ok1);
        if (has2) {
            const float* ip2 = in + c0*HWSZ + g2;
            uint32_t d2 = sb + so2*4;
            #pragma unroll
            for (int ci = 0; ci < C3_CHUNK; ci++)
                cp4(d2 + ci*(C3_CIS*4), ip2 + ci*HWSZ, ok2);
        }
        const float* wp1 = wt + wgo1 + c0*9;
        uint32_t dw1 = sb + (C3_BIN + wso1)*4;
        #pragma unroll
        for (int ci = 0; ci < C3_CHUNK; ci++)
            cp4(dw1 + ci*(288*4), wp1 + ci*9, true);
        if (wh2) {
            const float* wp2 = wt + wgo2 + c0*9;
            uint32_t dw2 = sb + (C3_BIN + wso2)*4;
            #pragma unroll
            for (int ci = 0; ci < C3_CHUNK; ci++)
                cp4(dw2 + ci*(288*4), wp2 + ci*9, true);
        }
    };

    u64 acc[4][4];
    #pragma unroll
    for (int cp = 0; cp < 4; cp++) {
        u64 b = pack2(__ldg(bs + cog*8 + 2*cp), __ldg(bs + cog*8 + 2*cp + 1));
        #pragma unroll
        for (int p = 0; p < 4; p++) acc[p][cp] = b;
    }

    stage(0, 0);
    CP_COMMIT();

    const int NCH = 32/C3_CHUNK;
    for (int ch = 0; ch < NCH; ch++) {
        int nb = ch & 1;
        if (ch + 1 < NCH) {
            stage(nb ^ 1, (ch+1)*C3_CHUNK);
            CP_COMMIT();
            CP_WAIT(1);
        } else {
            CP_WAIT(0);
        }
        __syncthreads();

        const float* s_in = sm + nb*C3_BUF;
        const float* s_w  = s_in + C3_BIN;
        for (int ci = 0; ci < C3_CHUNK; ci++) {
            const float* base = s_in + ci*C3_CIS + ty*C3_RS + txg*4;
            const float* wb   = s_w + ci*288 + cog*8;
            #pragma unroll
            for (int ky = 0; ky < 3; ky++) {
                const float* rp = base + ky*C3_RS;
                float4 v4 = *(const float4*)rp;
                float2 v2 = *(const float2*)(rp + 4);
                u64 vp[6];
                vp[0]=pack2(v4.x,v4.x); vp[1]=pack2(v4.y,v4.y); vp[2]=pack2(v4.z,v4.z);
                vp[3]=pack2(v4.w,v4.w); vp[4]=pack2(v2.x,v2.x); vp[5]=pack2(v2.y,v2.y);
                #pragma unroll
                for (int kx = 0; kx < 3; kx++) {
                    const ulonglong2* wq = (const ulonglong2*)(wb + (ky*3 + kx)*32);
                    ulonglong2 w0 = wq[0], w1 = wq[1];
                    u64 w[4] = {w0.x, w0.y, w1.x, w1.y};
                    #pragma unroll
                    for (int p = 0; p < 4; p++)
                        #pragma unroll
                        for (int cp = 0; cp < 4; cp++)
                            acc[p][cp] = fma2(vp[p+kx], w[cp], acc[p][cp]);
                }
            }
        }
        __syncthreads();
    }

    int o = (oy0 + ty)*WW + ox0 + txg*4;
    #pragma unroll
    for (int cp = 0; cp < 4; cp++) {
        int coe = cog*8 + 2*cp;
        float4 ve, vo;
        unpack2(acc[0][cp], ve.x, vo.x);
        unpack2(acc[1][cp], ve.y, vo.y);
        unpack2(acc[2][cp], ve.z, vo.z);
        unpack2(acc[3][cp], ve.w, vo.w);
        if (MODE == 0) {
            ve.x=fmaxf(ve.x,0.f); ve.y=fmaxf(ve.y,0.f); ve.z=fmaxf(ve.z,0.f); ve.w=fmaxf(ve.w,0.f);
            vo.x=fmaxf(vo.x,0.f); vo.y=fmaxf(vo.y,0.f); vo.z=fmaxf(vo.z,0.f); vo.w=fmaxf(vo.w,0.f);
        } else {
            float4 se = *(const float4*)(sk + coe*HWSZ + o);
            float4 so = *(const float4*)(sk + (coe+1)*HWSZ + o);
            ve.x+=se.x; ve.y+=se.y; ve.z+=se.z; ve.w+=se.w;
            vo.x+=so.x; vo.y+=so.y; vo.z+=so.z; vo.w+=so.w;
            ve.x=(ve.x>=0.f)?ve.x:0.2f*ve.x; ve.y=(ve.y>=0.f)?ve.y:0.2f*ve.y;
            ve.z=(ve.z>=0.f)?ve.z:0.2f*ve.z; ve.w=(ve.w>=0.f)?ve.w:0.2f*ve.w;
            vo.x=(vo.x>=0.f)?vo.x:0.2f*vo.x; vo.y=(vo.y>=0.f)?vo.y:0.2f*vo.y;
            vo.z=(vo.z>=0.f)?vo.z:0.2f*vo.z; vo.w=(vo.w>=0.f)?vo.w:0.2f*vo.w;
        }
        *(float4*)(out + coe*HWSZ + o)     = ve;
        *(float4*)(out + (coe+1)*HWSZ + o) = vo;
    }
}

// ---------------- 5x5 conv, CIN->32, pad 2, lrelu, dual image ----------------
// tile 64x4; thread = 4 px x 8 co; cp.async double-buffered, CHUNK param
#define C5_RS  68
#define C5_CIS (8*C5_RS)    // 544

template<int CIN, int CHUNK>
__global__ void __launch_bounds__(256, 3) conv5_k(
    const float* __restrict__ in0, const float* __restrict__ in1,
    const float* __restrict__ wt,  const float* __restrict__ bs,
    float* __restrict__ out0, float* __restrict__ out1)
{
    constexpr int BIN = CHUNK*C5_CIS;
    constexpr int BW  = CHUNK*800;
    constexpr int BUF = BIN + BW;
    extern __shared__ float sm[];
    const uint32_t smem0 = (uint32_t)__cvta_generic_to_shared(sm);
    const float* in = blockIdx.z ? in1 : in0;
    float* out      = blockIdx.z ? out1 : out0;
    const int tid = threadIdx.x;
    const int txg = tid & 15;
    const int ty  = (tid >> 4) & 3;
    const int cog = tid >> 6;
    const int ox0 = blockIdx.x*64, oy0 = blockIdx.y*4;

    // input per ci = 544 (8x68): slots tid, +256, +512(tid<32)
    const int ir[3] = { tid/68, (tid+256)/68, (tid+512)/68 };
    const int ic[3] = { tid%68, (tid+256)%68, (tid+512)%68 };
    const bool ihas[3] = { true, true, tid < 32 };
    bool iok[3]; int ig[3], iso[3];
    #pragma unroll
    for (int j = 0; j < 3; j++) {
        int y = oy0 - 2 + ir[j], x = ox0 - 2 + ic[j];
        iok[j] = ihas[j] && (y >= 0 && y < HH && x >= 0 && x < WW);
        ig[j]  = iok[j] ? (y*WW + x) : 0;
        iso[j] = ir[j]*C5_RS + ic[j];
    }
    // weights per ci = 800 (25k x 32co): slots tid+j*256, last only tid<32
    int wgo[4], wso[4]; bool whas[4];
    #pragma unroll
    for (int j = 0; j < 4; j++) {
        int e = tid + j*256;
        int k = e >> 5, co = e & 31;
        whas[j] = e < 800;
        wgo[j] = co*(CIN*25) + k;     // + (c0+ci)*25
        wso[j] = k*32 + co;
    }

    auto stage = [&](int nb, int c0) {
        uint32_t sb = smem0 + nb*(BUF*4);
        #pragma unroll
        for (int j = 0; j < 3; j++) {
            if (!ihas[j]) continue;
            const float* ip = in + c0*HWSZ + ig[j];
            uint32_t d = sb + iso[j]*4;
            #pragma unroll
            for (int ci = 0; ci < CHUNK; ci++)
                cp4(d + ci*(C5_CIS*4), ip + ci*HWSZ, iok[j]);
        }
        #pragma unroll
        for (int j = 0; j < 4; j++) {
            if (!whas[j]) continue;
            const float* wp = wt + wgo[j] + c0*25;
            uint32_t d = sb + (BIN + wso[j])*4;
            #pragma unroll
            for (int ci = 0; ci < CHUNK; ci++)
                cp4(d + ci*(800*4), wp + ci*25, true);
        }
    };

    u64 acc[4][4];
    #pragma unroll
    for (int cp = 0; cp < 4; cp++) {
        u64 b = pack2(__ldg(bs + cog*8 + 2*cp), __ldg(bs + cog*8 + 2*cp + 1));
        #pragma unroll
        for (int p = 0; p < 4; p++) acc[p][cp] = b;
    }

    stage(0, 0);
    CP_COMMIT();

    constexpr int NCH = CIN/CHUNK;
    for (int ch = 0; ch < NCH; ch++) {
        int nb = ch & 1;
        if (ch + 1 < NCH) {
            stage(nb ^ 1, (ch+1)*CHUNK);
            CP_COMMIT();
            CP_WAIT(1);
        } else {
            CP_WAIT(0);
        }
        __syncthreads();

        const float* s_in = sm + nb*BUF;
        const float* s_w  = s_in + BIN;
        for (int ci = 0; ci < CHUNK; ci++) {
            const float* base = s_in + ci*C5_CIS + ty*C5_RS + txg*4;
            const float* wb   = s_w + ci*800 + cog*8;
            #pragma unroll
            for (int ky = 0; ky < 5; ky++) {
                const float* rp = base + ky*C5_RS;
                float4 a4 = *(const float4*)rp;
                float4 b4 = *(const float4*)(rp + 4);
                u64 vp[8];
                vp[0]=pack2(a4.x,a4.x); vp[1]=pack2(a4.y,a4.y); vp[2]=pack2(a4.z,a4.z);
                vp[3]=pack2(a4.w,a4.w); vp[4]=pack2(b4.x,b4.x); vp[5]=pack2(b4.y,b4.y);
                vp[6]=pack2(b4.z,b4.z); vp[7]=pack2(b4.w,b4.w);
                #pragma unroll
                for (int kx = 0; kx < 5; kx++) {
                    const ulonglong2* wq = (const ulonglong2*)(wb + (ky*5 + kx)*32);
                    ulonglong2 w0 = wq[0], w1 = wq[1];
                    u64 w[4] = {w0.x, w0.y, w1.x, w1.y};
                    #pragma unroll
                    for (int p = 0; p < 4; p++)
                        #pragma unroll
                        for (int cp = 0; cp < 4; cp++)
                            acc[p][cp] = fma2(vp[p+kx], w[cp], acc[p][cp]);
                }
            }
        }
        __syncthreads();
    }

    int o = (oy0 + ty)*WW + ox0 + txg*4;
    #pragma unroll
    for (int cp = 0; cp < 4; cp++) {
        int coe = cog*8 + 2*cp;
        float4 ve, vo;
        unpack2(acc[0][cp], ve.x, vo.x);
        unpack2(acc[1][cp], ve.y, vo.y);
        unpack2(acc[2][cp], ve.z, vo.z);
        unpack2(acc[3][cp], ve.w, vo.w);
        ve.x=(ve.x>=0.f)?ve.x:0.2f*ve.x; ve.y=(ve.y>=0.f)?ve.y:0.2f*ve.y;
        ve.z=(ve.z>=0.f)?ve.z:0.2f*ve.z; ve.w=(ve.w>=0.f)?ve.w:0.2f*ve.w;
        vo.x=(vo.x>=0.f)?vo.x:0.2f*vo.x; vo.y=(vo.y>=0.f)?vo.y:0.2f*vo.y;
        vo.z=(vo.z>=0.f)?vo.z:0.2f*vo.z; vo.w=(vo.w>=0.f)?vo.w:0.2f*vo.w;
        *(float4*)(out + coe*HWSZ + o)     = ve;
        *(float4*)(out + (coe+1)*HWSZ + o) = vo;
    }
}

// ---------------- fused 1x1 affine head + deformable 2x2 bilinear sampler ----
__device__ __forceinline__ int reflect_idx(int i) {
    int r = i - 1;
    r = (r < 0) ? -r : r;
    r = (r > 319) ? (638 - r) : r;
    return r;
}

__global__ void sampler_k(const float* __restrict__ hid, const float* __restrict__ w2,
                          const float* __restrict__ b2, const float* __restrict__ x,
                          float* __restrict__ out) {
    __shared__ float s_w2[96];
    int tid = threadIdx.x;
    if (tid < 96) s_w2[tid] = w2[tid];
    __syncthreads();
    int p = blockIdx.x*256 + tid;
    int h = p / WW, w = p % WW;

    float a0 = __ldg(b2 + 0), a1 = __ldg(b2 + 1), a2 = __ldg(b2 + 2);
    #pragma unroll 4
    for (int c = 0; c < 32; c++) {
        float hv = hid[c*HWSZ + p];
        a0 += hv*s_w2[c];
        a1 += hv*s_w2[32 + c];
        a2 += hv*s_w2[64 + c];
    }
    a0 = fminf(fmaxf(a0 + 1.0f, -3.0f), 3.0f);
    a1 = fminf(fmaxf(a1 + 1.0f, -3.0f), 3.0f);
    a2 = fminf(fmaxf(a2 + 1.0f, -3.0f), 3.0f);
    float th = (a2 - 1.0f)*1.0472f;
    float ct = cosf(th), st = sinf(th);

    int   idx[16];
    float wg[16];
    #pragma unroll
    for (int k = 0; k < 4; k++) {
        float pnx = (k & 2) ? 0.5f : -0.5f;
        float pny = (k & 1) ? 0.5f : -0.5f;
        float px = pnx*a0, py = pny*a1;
        float rx = px*ct - py*st;
        float ry = px*st + py*ct;
        float p_x = rx + 0.5f + (float)(h + 1);
        float p_y = ry + 0.5f + (float)(w + 1);
        float ltx = floorf(p_x), lty = floorf(p_y);
        float ltxc = fminf(fmaxf(ltx,        0.0f), 321.0f);
        float ltyc = fminf(fmaxf(lty,        0.0f), 321.0f);
        float rbxc = fminf(fmaxf(ltx + 1.0f, 0.0f), 321.0f);
        float rbyc = fminf(fmaxf(lty + 1.0f, 0.0f), 321.0f);
        float pxc  = fminf(fmaxf(p_x,        0.0f), 321.0f);
        float pyc  = fminf(fmaxf(p_y,        0.0f), 321.0f);
        float wlx = 1.0f + ltxc - pxc;
        float wrx = 1.0f - (rbxc - pxc);
        float wly = 1.0f + ltyc - pyc;
        float wry = 1.0f - (rbyc - pyc);
        int rl = reflect_idx((int)ltxc);
        int rr = reflect_idx((int)rbxc);
        int cl = reflect_idx((int)ltyc);
        int cr = reflect_idx((int)rbyc);
        idx[k*4+0] = rl*WW + cl;  wg[k*4+0] = wlx*wly;
        idx[k*4+1] = rr*WW + cr;  wg[k*4+1] = wrx*wry;
        idx[k*4+2] = rl*WW + cr;  wg[k*4+2] = wlx*wry;
        idx[k*4+3] = rr*WW + cl;  wg[k*4+3] = wrx*wly;
    }

    int ob = (2*h)*640 + 2*w;
    for (int c = 0; c < 64; c++) {
        const float* xc = x + c*HWSZ;
        float* oc = out + c*640*640;
        float v[4];
        #pragma unroll
        for (int k = 0; k < 4; k++) {
            v[k] = wg[k*4+0]*__ldg(xc + idx[k*4+0])
                 + wg[k*4+1]*__ldg(xc + idx[k*4+1])
                 + wg[k*4+2]*__ldg(xc + idx[k*4+2])
                 + wg[k*4+3]*__ldg(xc + idx[k*4+3]);
        }
        *(float2*)(oc + ob)       = make_float2(v[0], v[1]);
        *(float2*)(oc + ob + 640) = make_float2(v[2], v[3]);
    }
}

// ---------------- launch ------------------------------------------------------
extern "C" void kernel_launch(void* const* d_in, const int* in_sizes, int n_in,
                              void* d_out, int out_size) {
    const float* x    = (const float*)d_in[0];
    const float* qry  = (const float*)d_in[1];
    const float* ref  = (const float*)d_in[2];
    const float* c1w  = (const float*)d_in[3];
    const float* c1b  = (const float*)d_in[4];
    const float* r1w1 = (const float*)d_in[5];
    const float* r1b1 = (const float*)d_in[6];
    const float* r1w2 = (const float*)d_in[7];
    const float* r1b2 = (const float*)d_in[8];
    const float* p1w  = (const float*)d_in[9];
    const float* p1b  = (const float*)d_in[10];
    const float* prw1 = (const float*)d_in[11];
    const float* prb1 = (const float*)d_in[12];
    const float* prw2 = (const float*)d_in[13];
    const float* prb2 = (const float*)d_in[14];
    const float* p2w  = (const float*)d_in[15];
    const float* p2b  = (const float*)d_in[16];
    float* out = (float*)d_out;

    float *up, *feat, *buf1, *buf2, *hid;
    cudaGetSymbolAddress((void**)&up,   g_up);
    cudaGetSymbolAddress((void**)&feat, g_feat);
    cudaGetSymbolAddress((void**)&buf1, g_buf1);
    cudaGetSymbolAddress((void**)&buf2, g_buf2);
    cudaGetSymbolAddress((void**)&hid,  g_hid);

    const int SM3    = C3_SMEM;                          // 44544 B
    const int SM5_3  = 2*(3*C5_CIS + 3*800)*4;           // 32256 B
    const int SM5_64 = 2*(4*C5_CIS + 4*800)*4;           // 43008 B
    cudaFuncSetAttribute(conv3_k<0>, cudaFuncAttributeMaxDynamicSharedMemorySize, SM3);
    cudaFuncSetAttribute(conv3_k<1>, cudaFuncAttributeMaxDynamicSharedMemorySize, SM3);
    cudaFuncSetAttribute(conv5_k<3,3>,  cudaFuncAttributeMaxDynamicSharedMemorySize, SM5_3);
    cudaFuncSetAttribute(conv5_k<64,4>, cudaFuncAttributeMaxDynamicSharedMemorySize, SM5_64);

    dim3 cg2(5, 80, 2);
    dim3 cg1(5, 80, 1);

    bicubic_k<<<(3*HWSZ)/256, 256>>>(qry, up);

    conv5_k<3,3><<<cg2, 256, SM5_3>>>(ref, up, c1w, c1b, buf1, buf1 + 32*HWSZ);
    conv3_k<0><<<cg2, 256, SM3>>>(buf1, buf1 + 32*HWSZ, r1w1, r1b1,
                                  nullptr, nullptr, buf2, buf2 + 32*HWSZ);
    conv3_k<1><<<cg2, 256, SM3>>>(buf2, buf2 + 32*HWSZ, r1w2, r1b2,
                                  buf1, buf1 + 32*HWSZ, feat, feat + 32*HWSZ);

    conv5_k<64,4><<<cg1, 256, SM5_64>>>(feat, feat, p1w, p1b, buf1, buf1);
    conv3_k<0><<<cg1, 256, SM3>>>(buf1, buf1, prw1, prb1, nullptr, nullptr, buf2, buf2);
    conv3_k<1><<<cg1, 256, SM3>>>(buf2, buf2, prw2, prb2, buf1, buf1, hid, hid);

    sampler_k<<<HWSZ/256, 256>>>(hid, p2w, p2b, x, out);
}

// round 10
// speedup vs baseline: 1.6022x; 1.2833x over previous
#include <cuda_runtime.h>
#include <math.h>
#include <stdint.h>

#define HH 320
#define WW 320
#define HWSZ (320*320)

// ---------------- scratch (static device globals; no allocation) -------------
__device__ float g_up[3*HWSZ];
__device__ float g_feat[64*HWSZ];
__device__ float g_buf1[64*HWSZ];
__device__ float g_buf2[64*HWSZ];
__device__ float g_hid[32*HWSZ];
__device__ float g_w3t[4*9216];    // 4 transposed 3x3 32->32 weights [ci][k][co]
__device__ float g_w5a[3*800];     // conv1 5x5 3->32  [ci][k][co]
__device__ float g_w5b[64*800];    // p1    5x5 64->32 [ci][k][co]

typedef unsigned long long u64;

// ---------------- packed f32x2 helpers (sm_103a FFMA2) -----------------------
__device__ __forceinline__ u64 pack2(float a, float b) {
    u64 r; asm("mov.b64 %0,{%1,%2};" : "=l"(r) : "f"(a), "f"(b)); return r;
}
__device__ __forceinline__ void unpack2(u64 v, float& a, float& b) {
    asm("mov.b64 {%0,%1},%2;" : "=f"(a), "=f"(b) : "l"(v));
}
__device__ __forceinline__ u64 fma2(u64 a, u64 b, u64 c) {
    u64 d; asm("fma.rn.f32x2 %0,%1,%2,%3;" : "=l"(d) : "l"(a), "l"(b), "l"(c)); return d;
}

// ---------------- cp.async helpers -------------------------------------------
__device__ __forceinline__ void cp4(uint32_t s, const float* g, bool ok) {
    int sz = ok ? 4 : 0;
    asm volatile("cp.async.ca.shared.global [%0], [%1], 4, %2;"
                 :: "r"(s), "l"(g), "r"(sz) : "memory");
}
__device__ __forceinline__ void cp16(uint32_t s, const float4* g) {
    asm volatile("cp.async.cg.shared.global [%0], [%1], 16;"
                 :: "r"(s), "l"(g) : "memory");
}
#define CP_COMMIT() asm volatile("cp.async.commit_group;" ::: "memory")
#define CP_WAIT(n)  asm volatile("cp.async.wait_group %0;" :: "n"(n) : "memory")

// ---------------- weight transpose pre-kernels -------------------------------
// conv3: src[(co*32+ci)*9+k] -> dst[ci*288 + k*32 + co], 9216 per tensor, 4 tensors
__global__ void tr3_k(const float* __restrict__ w0, const float* __restrict__ w1,
                      const float* __restrict__ w2, const float* __restrict__ w3,
                      float* __restrict__ dst) {
    int i = blockIdx.x*256 + threadIdx.x;          // 4*9216 = 36864 exact
    int n = i / 9216, e = i % 9216;
    const float* srcs[4] = {w0, w1, w2, w3};
    int co = e / 288, rem = e % 288, ci = rem / 9, k = rem % 9;
    dst[n*9216 + ci*288 + k*32 + co] = srcs[n][e];
}
// conv5: src[(co*CIN+ci)*25+k] -> dst[ci*800 + k*32 + co]
template<int CIN>
__global__ void tr5_k(const float* __restrict__ w, float* __restrict__ dst) {
    int i = blockIdx.x*256 + threadIdx.x;
    if (i >= 32*CIN*25) return;
    int co = i / (CIN*25), rem = i % (CIN*25), ci = rem / 25, k = rem % 25;
    dst[ci*800 + k*32 + co] = w[i];
}

// ---------------- bicubic x2 (A = -0.75) -------------------------------------
__device__ __forceinline__ float cubicw(float t) {
    t = fabsf(t);
    if (t <= 1.0f) return ((1.25f*t - 2.25f)*t)*t + 1.0f;
    if (t <  2.0f) return -0.75f*((((t - 5.0f)*t + 8.0f)*t) - 4.0f);
    return 0.0f;
}

__global__ void bicubic_k(const float* __restrict__ q, float* __restrict__ o) {
    int idx = blockIdx.x*256 + threadIdx.x;
    int ox = idx % 320;
    int t  = idx / 320;
    int oy = t % 320;
    int c  = t / 320;
    float sy = (oy + 0.5f)*0.5f - 0.5f;
    float sx = (ox + 0.5f)*0.5f - 0.5f;
    int iy0 = (int)floorf(sy), ix0 = (int)floorf(sx);
    float wy[4], wx[4]; int jy[4], jx[4];
    #pragma unroll
    for (int k = 0; k < 4; k++) {
        int ty = iy0 - 1 + k;
        wy[k] = cubicw(sy - (float)ty);
        jy[k] = min(max(ty, 0), 159);
        int tx = ix0 - 1 + k;
        wx[k] = cubicw(sx - (float)tx);
        jx[k] = min(max(tx, 0), 159);
    }
    const float* qc = q + c*160*160;
    float s = 0.0f;
    #pragma unroll
    for (int yy = 0; yy < 4; yy++) {
        float acc = 0.0f;
        #pragma unroll
        for (int xx = 0; xx < 4; xx++)
            acc += wx[xx]*__ldg(qc + jy[yy]*160 + jx[xx]);
        s += wy[yy]*acc;
    }
    o[idx] = s;
}

// ---------------- 3x3 conv, 32->32, pad 1, dual image ------------------------
// tile 64x4; thread = 4 px x 8 co; cp.async double-buffered; transposed weights
#define C3_CHUNK 8
#define C3_RS   68
#define C3_CIS  (6*C3_RS)                    // 408
#define C3_BIN  (C3_CHUNK*C3_CIS)            // 3264
#define C3_BW   (C3_CHUNK*288)               // 2304
#define C3_BUF  (C3_BIN + C3_BW)             // 5568 floats
#define C3_SMEM (2*C3_BUF*4)                 // 44544 B

template<int MODE>
__global__ void __launch_bounds__(256, 3) conv3_k(
    const float* __restrict__ in0, const float* __restrict__ in1,
    const float* __restrict__ wtT, const float* __restrict__ bs,
    const float* __restrict__ sk0, const float* __restrict__ sk1,
    float* __restrict__ out0, float* __restrict__ out1)
{
    extern __shared__ float sm[];
    const uint32_t smem0 = (uint32_t)__cvta_generic_to_shared(sm);
    const float* in = blockIdx.z ? in1 : in0;
    const float* sk = blockIdx.z ? sk1 : sk0;
    float* out      = blockIdx.z ? out1 : out0;
    const int tid = threadIdx.x;
    const int txg = tid & 15;
    const int ty  = (tid >> 4) & 3;
    const int cog = tid >> 6;
    const int ox0 = blockIdx.x*64, oy0 = blockIdx.y*4;

    // hoisted input staging maps: per ci 396 elems (6x66), slots tid, tid+256
    const int r1 = tid / 66,        c1 = tid % 66;
    const int r2 = (tid+256) / 66,  c2 = (tid+256) % 66;
    const bool has2 = tid < 140;
    const int y1 = oy0 - 1 + r1, x1 = ox0 - 1 + c1;
    const int y2 = oy0 - 1 + r2, x2 = ox0 - 1 + c2;
    const bool ok1 = (y1 >= 0 && y1 < HH && x1 >= 0 && x1 < WW);
    const bool ok2 = has2 && (y2 >= 0 && y2 < HH && x2 >= 0 && x2 < WW);
    const int g1 = ok1 ? (y1*WW + x1) : 0;
    const int g2 = ok2 ? (y2*WW + x2) : 0;
    const int so1 = r1*C3_RS + c1;
    const int so2 = r2*C3_RS + c2;

    auto stage = [&](int nb, int c0) {
        uint32_t sb = smem0 + nb*(C3_BUF*4);
        const float* ip1 = in + c0*HWSZ + g1;
        uint32_t d1 = sb + so1*4;
        #pragma unroll
        for (int ci = 0; ci < C3_CHUNK; ci++)
            cp4(d1 + ci*(C3_CIS*4), ip1 + ci*HWSZ, ok1);
        if (has2) {
            const float* ip2 = in + c0*HWSZ + g2;
            uint32_t d2 = sb + so2*4;
            #pragma unroll
            for (int ci = 0; ci < C3_CHUNK; ci++)
                cp4(d2 + ci*(C3_CIS*4), ip2 + ci*HWSZ, ok2);
        }
        // weights: contiguous CHUNK*288 floats = 576 float4 from transposed buf
        const float4* wsrc = (const float4*)(wtT + c0*288);
        uint32_t wdst = sb + C3_BIN*4;
        cp16(wdst + tid*16,        wsrc + tid);
        cp16(wdst + (tid+256)*16,  wsrc + tid + 256);
        if (tid < 64) cp16(wdst + (tid+512)*16, wsrc + tid + 512);
    };

    u64 acc[4][4];
    #pragma unroll
    for (int cp = 0; cp < 4; cp++) {
        u64 b = pack2(__ldg(bs + cog*8 + 2*cp), __ldg(bs + cog*8 + 2*cp + 1));
        #pragma unroll
        for (int p = 0; p < 4; p++) acc[p][cp] = b;
    }

    stage(0, 0);
    CP_COMMIT();

    const int NCH = 32/C3_CHUNK;
    for (int ch = 0; ch < NCH; ch++) {
        int nb = ch & 1;
        if (ch + 1 < NCH) {
            stage(nb ^ 1, (ch+1)*C3_CHUNK);
            CP_COMMIT();
            CP_WAIT(1);
        } else {
            CP_WAIT(0);
        }
        __syncthreads();

        const float* s_in = sm + nb*C3_BUF;
        const float* s_w  = s_in + C3_BIN;
        for (int ci = 0; ci < C3_CHUNK; ci++) {
            const float* base = s_in + ci*C3_CIS + ty*C3_RS + txg*4;
            const float* wb   = s_w + ci*288 + cog*8;
            #pragma unroll
            for (int ky = 0; ky < 3; ky++) {
                const float* rp = base + ky*C3_RS;
                float4 v4 = *(const float4*)rp;
                float2 v2 = *(const float2*)(rp + 4);
                u64 vp[6];
                vp[0]=pack2(v4.x,v4.x); vp[1]=pack2(v4.y,v4.y); vp[2]=pack2(v4.z,v4.z);
                vp[3]=pack2(v4.w,v4.w); vp[4]=pack2(v2.x,v2.x); vp[5]=pack2(v2.y,v2.y);
                #pragma unroll
                for (int kx = 0; kx < 3; kx++) {
                    const ulonglong2* wq = (const ulonglong2*)(wb + (ky*3 + kx)*32);
                    ulonglong2 w0 = wq[0], w1 = wq[1];
                    u64 w[4] = {w0.x, w0.y, w1.x, w1.y};
                    #pragma unroll
                    for (int p = 0; p < 4; p++)
                        #pragma unroll
                        for (int cp = 0; cp < 4; cp++)
                            acc[p][cp] = fma2(vp[p+kx], w[cp], acc[p][cp]);
                }
            }
        }
        __syncthreads();
    }

    int o = (oy0 + ty)*WW + ox0 + txg*4;
    #pragma unroll
    for (int cp = 0; cp < 4; cp++) {
        int coe = cog*8 + 2*cp;
        float4 ve, vo;
        unpack2(acc[0][cp], ve.x, vo.x);
        unpack2(acc[1][cp], ve.y, vo.y);
        unpack2(acc[2][cp], ve.z, vo.z);
        unpack2(acc[3][cp], ve.w, vo.w);
        if (MODE == 0) {
            ve.x=fmaxf(ve.x,0.f); ve.y=fmaxf(ve.y,0.f); ve.z=fmaxf(ve.z,0.f); ve.w=fmaxf(ve.w,0.f);
            vo.x=fmaxf(vo.x,0.f); vo.y=fmaxf(vo.y,0.f); vo.z=fmaxf(vo.z,0.f); vo.w=fmaxf(vo.w,0.f);
        } else {
            float4 se = *(const float4*)(sk + coe*HWSZ + o);
            float4 so = *(const float4*)(sk + (coe+1)*HWSZ + o);
            ve.x+=se.x; ve.y+=se.y; ve.z+=se.z; ve.w+=se.w;
            vo.x+=so.x; vo.y+=so.y; vo.z+=so.z; vo.w+=so.w;
            ve.x=(ve.x>=0.f)?ve.x:0.2f*ve.x; ve.y=(ve.y>=0.f)?ve.y:0.2f*ve.y;
            ve.z=(ve.z>=0.f)?ve.z:0.2f*ve.z; ve.w=(ve.w>=0.f)?ve.w:0.2f*ve.w;
            vo.x=(vo.x>=0.f)?vo.x:0.2f*vo.x; vo.y=(vo.y>=0.f)?vo.y:0.2f*vo.y;
            vo.z=(vo.z>=0.f)?vo.z:0.2f*vo.z; vo.w=(vo.w>=0.f)?vo.w:0.2f*vo.w;
        }
        *(float4*)(out + coe*HWSZ + o)     = ve;
        *(float4*)(out + (coe+1)*HWSZ + o) = vo;
    }
}

// ---------------- 5x5 conv, CIN->32, pad 2, lrelu, dual image ----------------
#define C5_RS  68
#define C5_CIS (8*C5_RS)    // 544

template<int CIN, int CHUNK>
__global__ void __launch_bounds__(256, 3) conv5_k(
    const float* __restrict__ in0, const float* __restrict__ in1,
    const float* __restrict__ wtT, const float* __restrict__ bs,
    float* __restrict__ out0, float* __restrict__ out1)
{
    constexpr int BIN = CHUNK*C5_CIS;
    constexpr int BW  = CHUNK*800;
    constexpr int BUF = BIN + BW;
    extern __shared__ float sm[];
    const uint32_t smem0 = (uint32_t)__cvta_generic_to_shared(sm);
    const float* in = blockIdx.z ? in1 : in0;
    float* out      = blockIdx.z ? out1 : out0;
    const int tid = threadIdx.x;
    const int txg = tid & 15;
    const int ty  = (tid >> 4) & 3;
    const int cog = tid >> 6;
    const int ox0 = blockIdx.x*64, oy0 = blockIdx.y*4;

    const int ir[3] = { tid/68, (tid+256)/68, (tid+512)/68 };
    const int ic[3] = { tid%68, (tid+256)%68, (tid+512)%68 };
    const bool ihas[3] = { true, true, tid < 32 };
    bool iok[3]; int ig[3], iso[3];
    #pragma unroll
    for (int j = 0; j < 3; j++) {
        int y = oy0 - 2 + ir[j], x = ox0 - 2 + ic[j];
        iok[j] = ihas[j] && (y >= 0 && y < HH && x >= 0 && x < WW);
        ig[j]  = iok[j] ? (y*WW + x) : 0;
        iso[j] = ir[j]*C5_RS + ic[j];
    }

    auto stage = [&](int nb, int c0) {
        uint32_t sb = smem0 + nb*(BUF*4);
        #pragma unroll
        for (int j = 0; j < 3; j++) {
            if (!ihas[j]) continue;
            const float* ip = in + c0*HWSZ + ig[j];
            uint32_t d = sb + iso[j]*4;
            #pragma unroll
            for (int ci = 0; ci < CHUNK; ci++)
                cp4(d + ci*(C5_CIS*4), ip + ci*HWSZ, iok[j]);
        }
        // weights: contiguous CHUNK*800 floats = CHUNK*200 float4
        const float4* wsrc = (const float4*)(wtT + c0*800);
        uint32_t wdst = sb + BIN*4;
        #pragma unroll
        for (int j = 0; j < (CHUNK*200 + 255)/256; j++) {
            int i = tid + j*256;
            if (i < CHUNK*200) cp16(wdst + i*16, wsrc + i);
        }
    };

    u64 acc[4][4];
    #pragma unroll
    for (int cp = 0; cp < 4; cp++) {
        u64 b = pack2(__ldg(bs + cog*8 + 2*cp), __ldg(bs + cog*8 + 2*cp + 1));
        #pragma unroll
        for (int p = 0; p < 4; p++) acc[p][cp] = b;
    }

    stage(0, 0);
    CP_COMMIT();

    constexpr int NCH = CIN/CHUNK;
    for (int ch = 0; ch < NCH; ch++) {
        int nb = ch & 1;
        if (ch + 1 < NCH) {
            stage(nb ^ 1, (ch+1)*CHUNK);
            CP_COMMIT();
            CP_WAIT(1);
        } else {
            CP_WAIT(0);
        }
        __syncthreads();

        const float* s_in = sm + nb*BUF;
        const float* s_w  = s_in + BIN;
        for (int ci = 0; ci < CHUNK; ci++) {
            const float* base = s_in + ci*C5_CIS + ty*C5_RS + txg*4;
            const float* wb   = s_w + ci*800 + cog*8;
            #pragma unroll
            for (int ky = 0; ky < 5; ky++) {
                const float* rp = base + ky*C5_RS;
                float4 a4 = *(const float4*)rp;
                float4 b4 = *(const float4*)(rp + 4);
                u64 vp[8];
                vp[0]=pack2(a4.x,a4.x); vp[1]=pack2(a4.y,a4.y); vp[2]=pack2(a4.z,a4.z);
                vp[3]=pack2(a4.w,a4.w); vp[4]=pack2(b4.x,b4.x); vp[5]=pack2(b4.y,b4.y);
                vp[6]=pack2(b4.z,b4.z); vp[7]=pack2(b4.w,b4.w);
                #pragma unroll
                for (int kx = 0; kx < 5; kx++) {
                    const ulonglong2* wq = (const ulonglong2*)(wb + (ky*5 + kx)*32);
                    ulonglong2 w0 = wq[0], w1 = wq[1];
                    u64 w[4] = {w0.x, w0.y, w1.x, w1.y};
                    #pragma unroll
                    for (int p = 0; p < 4; p++)
                        #pragma unroll
                        for (int cp = 0; cp < 4; cp++)
                            acc[p][cp] = fma2(vp[p+kx], w[cp], acc[p][cp]);
                }
            }
        }
        __syncthreads();
    }

    int o = (oy0 + ty)*WW + ox0 + txg*4;
    #pragma unroll
    for (int cp = 0; cp < 4; cp++) {
        int coe = cog*8 + 2*cp;
        float4 ve, vo;
        unpack2(acc[0][cp], ve.x, vo.x);
        unpack2(acc[1][cp], ve.y, vo.y);
        unpack2(acc[2][cp], ve.z, vo.z);
        unpack2(acc[3][cp], ve.w, vo.w);
        ve.x=(ve.x>=0.f)?ve.x:0.2f*ve.x; ve.y=(ve.y>=0.f)?ve.y:0.2f*ve.y;
        ve.z=(ve.z>=0.f)?ve.z:0.2f*ve.z; ve.w=(ve.w>=0.f)?ve.w:0.2f*ve.w;
        vo.x=(vo.x>=0.f)?vo.x:0.2f*vo.x; vo.y=(vo.y>=0.f)?vo.y:0.2f*vo.y;
        vo.z=(vo.z>=0.f)?vo.z:0.2f*vo.z; vo.w=(vo.w>=0.f)?vo.w:0.2f*vo.w;
        *(float4*)(out + coe*HWSZ + o)     = ve;
        *(float4*)(out + (coe+1)*HWSZ + o) = vo;
    }
}

// ---------------- fused 1x1 affine head + deformable 2x2 bilinear sampler ----
__device__ __forceinline__ int reflect_idx(int i) {
    int r = i - 1;
    r = (r < 0) ? -r : r;
    r = (r > 319) ? (638 - r) : r;
    return r;
}

__global__ void sampler_k(const float* __restrict__ hid, const float* __restrict__ w2,
                          const float* __restrict__ b2, const float* __restrict__ x,
                          float* __restrict__ out) {
    __shared__ float s_w2[96];
    int tid = threadIdx.x;
    if (tid < 96) s_w2[tid] = w2[tid];
    __syncthreads();
    int p = blockIdx.x*256 + tid;
    int h = p / WW, w = p % WW;

    float a0 = __ldg(b2 + 0), a1 = __ldg(b2 + 1), a2 = __ldg(b2 + 2);
    #pragma unroll 4
    for (int c = 0; c < 32; c++) {
        float hv = hid[c*HWSZ + p];
        a0 += hv*s_w2[c];
        a1 += hv*s_w2[32 + c];
        a2 += hv*s_w2[64 + c];
    }
    a0 = fminf(fmaxf(a0 + 1.0f, -3.0f), 3.0f);
    a1 = fminf(fmaxf(a1 + 1.0f, -3.0f), 3.0f);
    a2 = fminf(fmaxf(a2 + 1.0f, -3.0f), 3.0f);
    float th = (a2 - 1.0f)*1.0472f;
    float ct = cosf(th), st = sinf(th);

    int   idx[16];
    float wg[16];
    #pragma unroll
    for (int k = 0; k < 4; k++) {
        float pnx = (k & 2) ? 0.5f : -0.5f;
        float pny = (k & 1) ? 0.5f : -0.5f;
        float px = pnx*a0, py = pny*a1;
        float rx = px*ct - py*st;
        float ry = px*st + py*ct;
        float p_x = rx + 0.5f + (float)(h + 1);
        float p_y = ry + 0.5f + (float)(w + 1);
        float ltx = floorf(p_x), lty = floorf(p_y);
        float ltxc = fminf(fmaxf(ltx,        0.0f), 321.0f);
        float ltyc = fminf(fmaxf(lty,        0.0f), 321.0f);
        float rbxc = fminf(fmaxf(ltx + 1.0f, 0.0f), 321.0f);
        float rbyc = fminf(fmaxf(lty + 1.0f, 0.0f), 321.0f);
        float pxc  = fminf(fmaxf(p_x,        0.0f), 321.0f);
        float pyc  = fminf(fmaxf(p_y,        0.0f), 321.0f);
        float wlx = 1.0f + ltxc - pxc;
        float wrx = 1.0f - (rbxc - pxc);
        float wly = 1.0f + ltyc - pyc;
        float wry = 1.0f - (rbyc - pyc);
        int rl = reflect_idx((int)ltxc);
        int rr = reflect_idx((int)rbxc);
        int cl = reflect_idx((int)ltyc);
        int cr = reflect_idx((int)rbyc);
        idx[k*4+0] = rl*WW + cl;  wg[k*4+0] = wlx*wly;
        idx[k*4+1] = rr*WW + cr;  wg[k*4+1] = wrx*wry;
        idx[k*4+2] = rl*WW + cr;  wg[k*4+2] = wlx*wry;
        idx[k*4+3] = rr*WW + cl;  wg[k*4+3] = wrx*wly;
    }

    int ob = (2*h)*640 + 2*w;
    for (int c = 0; c < 64; c++) {
        const float* xc = x + c*HWSZ;
        float* oc = out + c*640*640;
        float v[4];
        #pragma unroll
        for (int k = 0; k < 4; k++) {
            v[k] = wg[k*4+0]*__ldg(xc + idx[k*4+0])
                 + wg[k*4+1]*__ldg(xc + idx[k*4+1])
                 + wg[k*4+2]*__ldg(xc + idx[k*4+2])
                 + wg[k*4+3]*__ldg(xc + idx[k*4+3]);
        }
        *(float2*)(oc + ob)       = make_float2(v[0], v[1]);
        *(float2*)(oc + ob + 640) = make_float2(v[2], v[3]);
    }
}

// ---------------- launch ------------------------------------------------------
extern "C" void kernel_launch(void* const* d_in, const int* in_sizes, int n_in,
                              void* d_out, int out_size) {
    const float* x    = (const float*)d_in[0];
    const float* qry  = (const float*)d_in[1];
    const float* ref  = (const float*)d_in[2];
    const float* c1w  = (const float*)d_in[3];
    const float* c1b  = (const float*)d_in[4];
    const float* r1w1 = (const float*)d_in[5];
    const float* r1b1 = (const float*)d_in[6];
    const float* r1w2 = (const float*)d_in[7];
    const float* r1b2 = (const float*)d_in[8];
    const float* p1w  = (const float*)d_in[9];
    const float* p1b  = (const float*)d_in[10];
    const float* prw1 = (const float*)d_in[11];
    const float* prb1 = (const float*)d_in[12];
    const float* prw2 = (const float*)d_in[13];
    const float* prb2 = (const float*)d_in[14];
    const float* p2w  = (const float*)d_in[15];
    const float* p2b  = (const float*)d_in[16];
    float* out = (float*)d_out;

    float *up, *feat, *buf1, *buf2, *hid, *w3t, *w5a, *w5b;
    cudaGetSymbolAddress((void**)&up,   g_up);
    cudaGetSymbolAddress((void**)&feat, g_feat);
    cudaGetSymbolAddress((void**)&buf1, g_buf1);
    cudaGetSymbolAddress((void**)&buf2, g_buf2);
    cudaGetSymbolAddress((void**)&hid,  g_hid);
    cudaGetSymbolAddress((void**)&w3t,  g_w3t);
    cudaGetSymbolAddress((void**)&w5a,  g_w5a);
    cudaGetSymbolAddress((void**)&w5b,  g_w5b);

    const int SM3    = C3_SMEM;                          // 44544 B
    const int SM5_3  = 2*(3*C5_CIS + 3*800)*4;           // 32256 B
    const int SM5_64 = 2*(4*C5_CIS + 4*800)*4;           // 43008 B
    cudaFuncSetAttribute(conv3_k<0>, cudaFuncAttributeMaxDynamicSharedMemorySize, SM3);
    cudaFuncSetAttribute(conv3_k<1>, cudaFuncAttributeMaxDynamicSharedMemorySize, SM3);
    cudaFuncSetAttribute(conv5_k<3,3>,  cudaFuncAttributeMaxDynamicSharedMemorySize, SM5_3);
    cudaFuncSetAttribute(conv5_k<64,4>, cudaFuncAttributeMaxDynamicSharedMemorySize, SM5_64);

    dim3 cg2(5, 80, 2);
    dim3 cg1(5, 80, 1);

    // 0. transpose weights to [ci][k][co] + bicubic upsample
    tr3_k<<<36864/256, 256>>>(r1w1, r1w2, prw1, prw2, w3t);
    tr5_k<3><<<(32*3*25 + 255)/256, 256>>>(c1w, w5a);
    tr5_k<64><<<(32*64*25 + 255)/256, 256>>>(p1w, w5b);
    bicubic_k<<<(3*HWSZ)/256, 256>>>(qry, up);

    // feature heads (dual image)
    conv5_k<3,3><<<cg2, 256, SM5_3>>>(ref, up, w5a, c1b, buf1, buf1 + 32*HWSZ);
    conv3_k<0><<<cg2, 256, SM3>>>(buf1, buf1 + 32*HWSZ, w3t, r1b1,
                                  nullptr, nullptr, buf2, buf2 + 32*HWSZ);
    conv3_k<1><<<cg2, 256, SM3>>>(buf2, buf2 + 32*HWSZ, w3t + 9216, r1b2,
                                  buf1, buf1 + 32*HWSZ, feat, feat + 32*HWSZ);

    // fusion head
    conv5_k<64,4><<<cg1, 256, SM5_64>>>(feat, feat, w5b, p1b, buf1, buf1);
    conv3_k<0><<<cg1, 256, SM3>>>(buf1, buf1, w3t + 2*9216, prb1, nullptr, nullptr, buf2, buf2);
    conv3_k<1><<<cg1, 256, SM3>>>(buf2, buf2, w3t + 3*9216, prb2, buf1, buf1, hid, hid);

    sampler_k<<<HWSZ/256, 256>>>(hid, p2w, p2b, x, out);
}